// round 1
// baseline (speedup 1.0000x reference)
#include <cuda_runtime.h>
#include <math.h>

#define TOK    4096      // B*L tokens
#define DMODEL 1024
#define QKVN   3072
#define NHEAD  16
#define HDIM   64
#define LSEQ   2048
#define NBATCH 2
#define WIN    128

// scratch (static device globals — no runtime allocation)
__device__ float g_qkv[TOK * QKVN];        // [token, 3*D]  (q | k | v)
__device__ float g_headout[TOK * DMODEL];  // [token, h*64+d]

// ---------------------------------------------------------------------------
// fp32 SGEMM with bias: C[M,N] = A[M,K] @ B[K,N] + bias[N]
// 128x128x8 tile, 256 threads, 8x8 per-thread microtile.
// ---------------------------------------------------------------------------
__global__ __launch_bounds__(256) void sgemm_bias(
    const float* __restrict__ A, const float* __restrict__ B,
    const float* __restrict__ bias, float* __restrict__ C,
    int M, int N, int K)
{
    __shared__ float As[8][128];
    __shared__ float Bs[8][128];

    const int tid  = threadIdx.x;
    const int brow = blockIdx.y, bcol = blockIdx.x;
    const int ar = tid >> 1, ac = (tid & 1) * 4;    // A tile load: 128 rows x 8 cols
    const int br = tid >> 5, bc = (tid & 31) * 4;   // B tile load: 8 rows x 128 cols
    const int ty = tid >> 4, tx = tid & 15;

    const float* Ap = A + (size_t)(brow * 128 + ar) * K + ac;
    const float* Bp = B + (size_t)br * N + bcol * 128 + bc;

    float acc[8][8];
#pragma unroll
    for (int i = 0; i < 8; i++)
#pragma unroll
        for (int j = 0; j < 8; j++) acc[i][j] = 0.f;

    for (int k0 = 0; k0 < K; k0 += 8) {
        float4 av = *(const float4*)(Ap + k0);
        float4 bv = *(const float4*)(Bp + (size_t)k0 * N);
        As[ac + 0][ar] = av.x;
        As[ac + 1][ar] = av.y;
        As[ac + 2][ar] = av.z;
        As[ac + 3][ar] = av.w;
        *(float4*)&Bs[br][bc] = bv;
        __syncthreads();
#pragma unroll
        for (int kk = 0; kk < 8; kk++) {
            float a[8];
#pragma unroll
            for (int i = 0; i < 8; i++) a[i] = As[kk][ty * 8 + i];
            float4 b0 = *(const float4*)&Bs[kk][tx * 8];
            float4 b1 = *(const float4*)&Bs[kk][tx * 8 + 4];
            float bb[8] = {b0.x, b0.y, b0.z, b0.w, b1.x, b1.y, b1.z, b1.w};
#pragma unroll
            for (int i = 0; i < 8; i++)
#pragma unroll
                for (int j = 0; j < 8; j++) acc[i][j] += a[i] * bb[j];
        }
        __syncthreads();
    }

#pragma unroll
    for (int i = 0; i < 8; i++) {
        int row = brow * 128 + ty * 8 + i;
        float* Cp = C + (size_t)row * N + bcol * 128 + tx * 8;
#pragma unroll
        for (int j = 0; j < 8; j++)
            Cp[j] = acc[i][j] + bias[bcol * 128 + tx * 8 + j];
    }
}

// ---------------------------------------------------------------------------
// Sliding-window attention. One block = 128 queries of one (b,h); one thread
// = one query. Window=128 => each query attends to exactly the 128 keys
// [q-127, q] (clamped at 0). Those keys live in two 128-key chunks:
//   chunk0 = [q0-128, q0)  -> thread t uses j in [t+1, 128)
//   chunk1 = [q0,    q0+128) -> thread t uses j in [0, t]
// Score index i in [0,128): key = q-127+i.
// Writes normalized weights into the (pre-zeroed) attn band and the per-head
// context vectors into g_headout laid out [token, h*64+d] for the proj GEMM.
// ---------------------------------------------------------------------------
__global__ __launch_bounds__(128) void attn_kernel(
    const float* __restrict__ qkv,
    float* __restrict__ attn,        // [B, H, L, L], already zeroed
    float* __restrict__ head_out)    // [token, D]
{
    const int qt = blockIdx.x, h = blockIdx.y, b = blockIdx.z;
    const int t  = threadIdx.x;
    const int q0 = qt * 128;
    const int q  = q0 + t;

    __shared__ float KVs[128][65];   // +1 pad: lane stride 65 == conflict-free

    // per-thread query vector (pre-scaled by 1/sqrt(64))
    float qreg[64];
    {
        const float* qp = qkv + (size_t)(b * LSEQ + q) * QKVN + h * HDIM;
#pragma unroll
        for (int d = 0; d < 64; d += 4) {
            float4 v = *(const float4*)(qp + d);
            qreg[d]     = v.x * 0.125f;
            qreg[d + 1] = v.y * 0.125f;
            qreg[d + 2] = v.z * 0.125f;
            qreg[d + 3] = v.w * 0.125f;
        }
    }

    float s[128];
    float m = -INFINITY;

    // ---- pass 1: scores over K ----
#pragma unroll
    for (int c = 0; c < 2; c++) {
        const int kb = q0 + (c - 1) * 128;
        __syncthreads();
        for (int idx = t; idx < 128 * 64; idx += 128) {
            int r = idx >> 6, d = idx & 63;
            int kk = kb + r;
            KVs[r][d] = (kk >= 0)
                ? qkv[(size_t)(b * LSEQ + kk) * QKVN + DMODEL + h * HDIM + d]
                : 0.f;
        }
        __syncthreads();
        const int jlo   = (c == 0) ? (t + 1) : 0;
        const int jhi   = (c == 0) ? 128 : (t + 1);
        const int ibase = (c == 0) ? (-t - 1) : (127 - t);
        for (int j = jlo; j < jhi; j++) {
            float acc = 0.f;
#pragma unroll
            for (int d = 0; d < 64; d++) acc += qreg[d] * KVs[j][d];
            if (kb + j < 0) acc = -INFINITY;   // key index < 0 (only near q=0)
            s[ibase + j] = acc;
            m = fmaxf(m, acc);
        }
    }

    // ---- softmax + write attention band ----
    const int lo = (q >= 127) ? 0 : (127 - q);   // first valid i
    float sum = 0.f;
    for (int i = lo; i < 128; i++) {
        float e = __expf(s[i] - m);
        s[i] = e;
        sum += e;
    }
    const float inv = 1.f / sum;
    float* arow = attn + ((size_t)(b * NHEAD + h) * LSEQ + q) * (size_t)LSEQ;
    for (int i = lo; i < 128; i++) {
        s[i] *= inv;
        arow[q - 127 + i] = s[i];
    }
    for (int i = 0; i < lo; i++) s[i] = 0.f;     // safe zeros for V pass

    // ---- pass 2: context = P @ V ----
    float o[64];
#pragma unroll
    for (int d = 0; d < 64; d++) o[d] = 0.f;

#pragma unroll
    for (int c = 0; c < 2; c++) {
        const int kb = q0 + (c - 1) * 128;
        __syncthreads();
        for (int idx = t; idx < 128 * 64; idx += 128) {
            int r = idx >> 6, d = idx & 63;
            int kk = kb + r;
            KVs[r][d] = (kk >= 0)
                ? qkv[(size_t)(b * LSEQ + kk) * QKVN + 2 * DMODEL + h * HDIM + d]
                : 0.f;
        }
        __syncthreads();
        const int jlo   = (c == 0) ? (t + 1) : 0;
        const int jhi   = (c == 0) ? 128 : (t + 1);
        const int ibase = (c == 0) ? (-t - 1) : (127 - t);
        for (int j = jlo; j < jhi; j++) {
            float p = s[ibase + j];
#pragma unroll
            for (int d = 0; d < 64; d++) o[d] += p * KVs[j][d];
        }
    }

    float* op = head_out + (size_t)(b * LSEQ + q) * DMODEL + h * HDIM;
#pragma unroll
    for (int d = 0; d < 64; d += 4) {
        float4 v;
        v.x = o[d]; v.y = o[d + 1]; v.z = o[d + 2]; v.w = o[d + 3];
        *(float4*)(op + d) = v;
    }
}

// ---------------------------------------------------------------------------
// kernel_launch: qkv GEMM -> attention (+ attn-weights write) -> proj GEMM.
// d_out layout (reference returns (out, attn_weights)):
//   [0, 4194304)            out          [B, L, D]
//   [4194304, 138412032)    attn_weights [B, H, L, L]
// ---------------------------------------------------------------------------
extern "C" void kernel_launch(void* const* d_in, const int* in_sizes, int n_in,
                              void* d_out, int out_size)
{
    const float* x      = (const float*)d_in[0];
    const float* W_qkv  = (const float*)d_in[1];
    const float* b_qkv  = (const float*)d_in[2];
    const float* W_proj = (const float*)d_in[3];
    const float* b_proj = (const float*)d_in[4];
    (void)in_sizes; (void)n_in; (void)out_size;   // window_size fixed at 128

    float* out  = (float*)d_out;
    float* attn = out + (size_t)NBATCH * LSEQ * DMODEL;

    float* qkv  = nullptr;
    float* hout = nullptr;
    cudaGetSymbolAddress((void**)&qkv,  g_qkv);
    cudaGetSymbolAddress((void**)&hout, g_headout);

    // zero the attention-weight tensor (band writes fill the valid window)
    cudaMemsetAsync(attn, 0, (size_t)NBATCH * NHEAD * LSEQ * LSEQ * sizeof(float));

    // qkv = x @ W_qkv + b_qkv
    sgemm_bias<<<dim3(QKVN / 128, TOK / 128), 256>>>(
        x, W_qkv, b_qkv, qkv, TOK, QKVN, DMODEL);

    // sliding-window attention
    attn_kernel<<<dim3(LSEQ / 128, NHEAD, NBATCH), 128>>>(qkv, attn, hout);

    // out = head_out @ W_proj + b_proj
    sgemm_bias<<<dim3(DMODEL / 128, TOK / 128), 256>>>(
        hout, W_proj, b_proj, out, TOK, DMODEL, DMODEL);
}

// round 3
// speedup vs baseline: 1.7554x; 1.7554x over previous
#include <cuda_runtime.h>
#include <math.h>
#include <stdint.h>

#define TOK    4096
#define DMODEL 1024
#define QKVN   3072
#define NHEAD  16
#define HDIM   64
#define LSEQ   2048
#define NBATCH 2

// ------------------------- static device scratch ---------------------------
__device__ float g_qkv[TOK * QKVN];        // [token, 3D]
__device__ float g_headout[TOK * DMODEL];  // [token, D]
__device__ float g_x32[TOK * DMODEL];      // tf32-rounded hidden states
__device__ float g_wqkvT[QKVN * DMODEL];   // W_qkv^T [N,K] tf32-rounded
__device__ float g_wprojT[DMODEL * DMODEL];// W_proj^T [N,K] tf32-rounded

__device__ __forceinline__ float round_tf32f(float x) {
    uint32_t u;
    asm("cvt.rna.tf32.f32 %0, %1;" : "=r"(u) : "f"(x));
    return __uint_as_float(u);
}

// ---------------------------------------------------------------------------
// tf32 mma.sync GEMM: C[M,N] = A[M,K] @ Bt[N,K]^T + bias[N]
// CTA 128x128x16, 256 threads = 8 warps (4 along M x 2 along N),
// warp tile 32x64, fragments via m16n8k8.row.col.f32.tf32.tf32.f32.
// SMEM tiles stored K-major with row stride 20 floats (conflict-free frags).
// ---------------------------------------------------------------------------
#define BM 128
#define BN 128
#define BK 16
#define LDT 20   // smem row stride in floats

__global__ __launch_bounds__(256, 2) void tf32_mma_gemm(
    const float* __restrict__ A, const float* __restrict__ Bt,
    const float* __restrict__ bias, float* __restrict__ C,
    int M, int N, int K)
{
    __shared__ float As[2][BM * LDT];
    __shared__ float Bs[2][BN * LDT];

    const int tid  = threadIdx.x;
    const int wid  = tid >> 5, lane = tid & 31;
    const int g    = lane >> 2, tg = lane & 3;      // groupID, threadInGroup
    const int wm   = (wid & 3) * 32;                // warp M offset in tile
    const int wn   = (wid >> 2) * 64;               // warp N offset in tile
    const int m0   = blockIdx.y * BM, n0 = blockIdx.x * BN;

    // gmem load mapping: 2 float4 per operand per thread (rows lr, lr+64)
    const int lr = tid >> 2;          // 0..63
    const int lc = (tid & 3) * 4;     // 0,4,8,12
    const float* Ag = A  + (size_t)(m0 + lr) * K + lc;
    const float* Bg = Bt + (size_t)(n0 + lr) * K + lc;

    float c[2][8][4];
#pragma unroll
    for (int i = 0; i < 2; i++)
#pragma unroll
        for (int j = 0; j < 8; j++)
#pragma unroll
            for (int r = 0; r < 4; r++) c[i][j][r] = 0.f;

    // prologue: load k-tile 0
    float4 ra0 = *(const float4*)(Ag);
    float4 ra1 = *(const float4*)(Ag + (size_t)64 * K);
    float4 rb0 = *(const float4*)(Bg);
    float4 rb1 = *(const float4*)(Bg + (size_t)64 * K);
    *(float4*)&As[0][lr * LDT + lc]        = ra0;
    *(float4*)&As[0][(lr + 64) * LDT + lc] = ra1;
    *(float4*)&Bs[0][lr * LDT + lc]        = rb0;
    *(float4*)&Bs[0][(lr + 64) * LDT + lc] = rb1;
    __syncthreads();

    const int niter = K / BK;
    for (int kt = 0; kt < niter; kt++) {
        const int cur = kt & 1;
        // prefetch next k-tile into registers
        if (kt + 1 < niter) {
            const float* An = Ag + (kt + 1) * BK;
            const float* Bn = Bg + (kt + 1) * BK;
            ra0 = *(const float4*)(An);
            ra1 = *(const float4*)(An + (size_t)64 * K);
            rb0 = *(const float4*)(Bn);
            rb1 = *(const float4*)(Bn + (size_t)64 * K);
        }

        // compute two k8 steps on the current buffer
#pragma unroll
        for (int kk = 0; kk < BK; kk += 8) {
            uint32_t a[2][4], b[8][2];
#pragma unroll
            for (int i = 0; i < 2; i++) {
                const int row = wm + i * 16 + g;
                a[i][0] = __float_as_uint(As[cur][row * LDT + kk + tg]);
                a[i][1] = __float_as_uint(As[cur][(row + 8) * LDT + kk + tg]);
                a[i][2] = __float_as_uint(As[cur][row * LDT + kk + tg + 4]);
                a[i][3] = __float_as_uint(As[cur][(row + 8) * LDT + kk + tg + 4]);
            }
#pragma unroll
            for (int j = 0; j < 8; j++) {
                const int col = wn + j * 8 + g;
                b[j][0] = __float_as_uint(Bs[cur][col * LDT + kk + tg]);
                b[j][1] = __float_as_uint(Bs[cur][col * LDT + kk + tg + 4]);
            }
#pragma unroll
            for (int i = 0; i < 2; i++)
#pragma unroll
                for (int j = 0; j < 8; j++) {
                    asm volatile(
                        "mma.sync.aligned.m16n8k8.row.col.f32.tf32.tf32.f32 "
                        "{%0,%1,%2,%3}, {%4,%5,%6,%7}, {%8,%9}, {%0,%1,%2,%3};"
                        : "+f"(c[i][j][0]), "+f"(c[i][j][1]),
                          "+f"(c[i][j][2]), "+f"(c[i][j][3])
                        : "r"(a[i][0]), "r"(a[i][1]), "r"(a[i][2]), "r"(a[i][3]),
                          "r"(b[j][0]), "r"(b[j][1]));
                }
        }

        // stage prefetched tile into the other buffer
        if (kt + 1 < niter) {
            const int nxt = cur ^ 1;
            *(float4*)&As[nxt][lr * LDT + lc]        = ra0;
            *(float4*)&As[nxt][(lr + 64) * LDT + lc] = ra1;
            *(float4*)&Bs[nxt][lr * LDT + lc]        = rb0;
            *(float4*)&Bs[nxt][(lr + 64) * LDT + lc] = rb1;
        }
        __syncthreads();
    }

    // epilogue: C = acc + bias
#pragma unroll
    for (int i = 0; i < 2; i++) {
        const int rowa = m0 + wm + i * 16 + g;
#pragma unroll
        for (int j = 0; j < 8; j++) {
            const int col = n0 + wn + j * 8 + 2 * tg;
            const float bx = bias[col], by = bias[col + 1];
            float2 v0 = make_float2(c[i][j][0] + bx, c[i][j][1] + by);
            float2 v1 = make_float2(c[i][j][2] + bx, c[i][j][3] + by);
            *(float2*)(C + (size_t)rowa * N + col)       = v0;
            *(float2*)(C + (size_t)(rowa + 8) * N + col) = v1;
        }
    }
}

// ---------------------------------------------------------------------------
// prep kernels: tf32-round copy, and transpose+round ( [K][N] -> [N][K] )
// ---------------------------------------------------------------------------
__global__ void round_copy(const float4* __restrict__ in, float4* __restrict__ out, int n4) {
    int i = blockIdx.x * 256 + threadIdx.x;
    if (i < n4) {
        float4 v = in[i];
        v.x = round_tf32f(v.x); v.y = round_tf32f(v.y);
        v.z = round_tf32f(v.z); v.w = round_tf32f(v.w);
        out[i] = v;
    }
}

__global__ __launch_bounds__(256) void transpose_round(
    const float* __restrict__ in, float* __restrict__ out, int K, int N)
{
    __shared__ float t[32][33];
    int bx = blockIdx.x * 32, by = blockIdx.y * 32;
    int x = threadIdx.x, y = threadIdx.y;   // block (32, 8)
#pragma unroll
    for (int i = 0; i < 32; i += 8)
        t[y + i][x] = in[(size_t)(by + y + i) * N + bx + x];
    __syncthreads();
#pragma unroll
    for (int i = 0; i < 32; i += 8)
        out[(size_t)(bx + y + i) * K + by + x] = round_tf32f(t[x][y + i]);
}

// ---------------------------------------------------------------------------
// Sliding-window attention; zero-fills its own 128x2048 attn tile and writes
// tf32-rounded head_out for the proj GEMM.
// ---------------------------------------------------------------------------
__global__ __launch_bounds__(128) void attn_kernel(
    const float* __restrict__ qkv,
    float* __restrict__ attn,        // [B, H, L, L]
    float* __restrict__ head_out)    // [token, D]
{
    const int qt = blockIdx.x, h = blockIdx.y, b = blockIdx.z;
    const int t  = threadIdx.x;
    const int q0 = qt * 128;
    const int q  = q0 + t;

    __shared__ float KVs[128][65];

    // zero the block's 128x2048 attn tile (coalesced float4 stores)
    {
        float4* zb = (float4*)(attn + ((size_t)(b * NHEAD + h) * LSEQ + q0) * (size_t)LSEQ);
        float4 z = make_float4(0.f, 0.f, 0.f, 0.f);
        for (int i = t; i < 128 * LSEQ / 4; i += 128) zb[i] = z;
    }

    float qreg[64];
    {
        const float* qp = qkv + (size_t)(b * LSEQ + q) * QKVN + h * HDIM;
#pragma unroll
        for (int d = 0; d < 64; d += 4) {
            float4 v = *(const float4*)(qp + d);
            qreg[d]     = v.x * 0.125f;
            qreg[d + 1] = v.y * 0.125f;
            qreg[d + 2] = v.z * 0.125f;
            qreg[d + 3] = v.w * 0.125f;
        }
    }

    float s[128];
    float m = -INFINITY;

    // ---- pass 1: scores over K ----
#pragma unroll
    for (int c = 0; c < 2; c++) {
        const int kb = q0 + (c - 1) * 128;
        __syncthreads();
        for (int idx = t; idx < 128 * 64; idx += 128) {
            int r = idx >> 6, d = idx & 63;
            int kk = kb + r;
            KVs[r][d] = (kk >= 0)
                ? qkv[(size_t)(b * LSEQ + kk) * QKVN + DMODEL + h * HDIM + d]
                : 0.f;
        }
        __syncthreads();
        const int jlo   = (c == 0) ? (t + 1) : 0;
        const int jhi   = (c == 0) ? 128 : (t + 1);
        const int ibase = (c == 0) ? (-t - 1) : (127 - t);
        for (int j = jlo; j < jhi; j++) {
            float acc = 0.f;
#pragma unroll
            for (int d = 0; d < 64; d++) acc += qreg[d] * KVs[j][d];
            if (kb + j < 0) acc = -INFINITY;
            s[ibase + j] = acc;
            m = fmaxf(m, acc);
        }
    }

    // ---- softmax + band write ----
    const int lo = (q >= 127) ? 0 : (127 - q);
    float sum = 0.f;
    for (int i = lo; i < 128; i++) {
        float e = __expf(s[i] - m);
        s[i] = e;
        sum += e;
    }
    const float inv = 1.f / sum;
    float* arow = attn + ((size_t)(b * NHEAD + h) * LSEQ + q) * (size_t)LSEQ;
    for (int i = lo; i < 128; i++) {
        s[i] *= inv;
        arow[q - 127 + i] = s[i];
    }
    for (int i = 0; i < lo; i++) s[i] = 0.f;

    // ---- pass 2: context = P @ V ----
    float o[64];
#pragma unroll
    for (int d = 0; d < 64; d++) o[d] = 0.f;

#pragma unroll
    for (int c = 0; c < 2; c++) {
        const int kb = q0 + (c - 1) * 128;
        __syncthreads();
        for (int idx = t; idx < 128 * 64; idx += 128) {
            int r = idx >> 6, d = idx & 63;
            int kk = kb + r;
            KVs[r][d] = (kk >= 0)
                ? qkv[(size_t)(b * LSEQ + kk) * QKVN + 2 * DMODEL + h * HDIM + d]
                : 0.f;
        }
        __syncthreads();
        const int jlo   = (c == 0) ? (t + 1) : 0;
        const int jhi   = (c == 0) ? 128 : (t + 1);
        const int ibase = (c == 0) ? (-t - 1) : (127 - t);
        for (int j = jlo; j < jhi; j++) {
            float p = s[ibase + j];
#pragma unroll
            for (int d = 0; d < 64; d++) o[d] += p * KVs[j][d];
        }
    }

    float* op = head_out + (size_t)(b * LSEQ + q) * DMODEL + h * HDIM;
#pragma unroll
    for (int d = 0; d < 64; d += 4) {
        float4 v;
        v.x = round_tf32f(o[d]);
        v.y = round_tf32f(o[d + 1]);
        v.z = round_tf32f(o[d + 2]);
        v.w = round_tf32f(o[d + 3]);
        *(float4*)(op + d) = v;
    }
}

// ---------------------------------------------------------------------------
extern "C" void kernel_launch(void* const* d_in, const int* in_sizes, int n_in,
                              void* d_out, int out_size)
{
    const float* x      = (const float*)d_in[0];
    const float* W_qkv  = (const float*)d_in[1];
    const float* b_qkv  = (const float*)d_in[2];
    const float* W_proj = (const float*)d_in[3];
    const float* b_proj = (const float*)d_in[4];
    (void)in_sizes; (void)n_in; (void)out_size;

    float* out  = (float*)d_out;
    float* attn = out + (size_t)NBATCH * LSEQ * DMODEL;

    float *qkv = nullptr, *hout = nullptr, *x32 = nullptr, *wqkvT = nullptr, *wprojT = nullptr;
    cudaGetSymbolAddress((void**)&qkv,    g_qkv);
    cudaGetSymbolAddress((void**)&hout,   g_headout);
    cudaGetSymbolAddress((void**)&x32,    g_x32);
    cudaGetSymbolAddress((void**)&wqkvT,  g_wqkvT);
    cudaGetSymbolAddress((void**)&wprojT, g_wprojT);

    // prep: tf32 rounding + weight transposes
    round_copy<<<(TOK * DMODEL / 4 + 255) / 256, 256>>>((const float4*)x, (float4*)x32, TOK * DMODEL / 4);
    transpose_round<<<dim3(QKVN / 32, DMODEL / 32), dim3(32, 8)>>>(W_qkv, wqkvT, DMODEL, QKVN);
    transpose_round<<<dim3(DMODEL / 32, DMODEL / 32), dim3(32, 8)>>>(W_proj, wprojT, DMODEL, DMODEL);

    // qkv = x @ W_qkv + b_qkv   (tf32 mma.sync)
    tf32_mma_gemm<<<dim3(QKVN / 128, TOK / 128), 256>>>(
        x32, wqkvT, b_qkv, qkv, TOK, QKVN, DMODEL);

    // sliding-window attention (+ fused attn-tile zeroing)
    attn_kernel<<<dim3(LSEQ / 128, NHEAD, NBATCH), 128>>>(qkv, attn, hout);

    // out = head_out @ W_proj + b_proj   (tf32 mma.sync)
    tf32_mma_gemm<<<dim3(DMODEL / 128, TOK / 128), 256>>>(
        hout, wprojT, b_proj, out, TOK, DMODEL, DMODEL);
}

// round 5
// speedup vs baseline: 2.1537x; 1.2269x over previous
#include <cuda_runtime.h>
#include <math.h>
#include <stdint.h>

#define TOK    4096
#define DMODEL 1024
#define QKVN   3072
#define NHEAD  16
#define HDIM   64
#define LSEQ   2048
#define NBATCH 2

// ------------------------- static device scratch ---------------------------
__device__ float g_qkv[TOK * QKVN];        // [token, 3D]
__device__ float g_headout[TOK * DMODEL];  // [token, D]
__device__ float g_x32[TOK * DMODEL];      // tf32-rounded hidden states
__device__ float g_wqkvT[QKVN * DMODEL];   // W_qkv^T [N,K] tf32-rounded
__device__ float g_wprojT[DMODEL * DMODEL];// W_proj^T [N,K] tf32-rounded

__device__ __forceinline__ float round_tf32f(float x) {
    uint32_t u;
    asm("cvt.rna.tf32.f32 %0, %1;" : "=r"(u) : "f"(x));
    return __uint_as_float(u);
}
__device__ __forceinline__ uint32_t tf32u(float x) {
    uint32_t u;
    asm("cvt.rna.tf32.f32 %0, %1;" : "=r"(u) : "f"(x));
    return u;
}

#define MMA_TF32(C, A0, A1, A2, A3, B0, B1)                                    \
    asm volatile(                                                              \
        "mma.sync.aligned.m16n8k8.row.col.f32.tf32.tf32.f32 "                  \
        "{%0,%1,%2,%3}, {%4,%5,%6,%7}, {%8,%9}, {%0,%1,%2,%3};"                \
        : "+f"((C)[0]), "+f"((C)[1]), "+f"((C)[2]), "+f"((C)[3])               \
        : "r"(A0), "r"(A1), "r"(A2), "r"(A3), "r"(B0), "r"(B1))

// ---------------------------------------------------------------------------
// tf32 mma.sync GEMM: C[M,N] = A[M,K] @ Bt[N,K]^T + bias[N]   (unchanged)
// ---------------------------------------------------------------------------
#define BM 128
#define BN 128
#define BK 16
#define LDT 20

__global__ __launch_bounds__(256, 2) void tf32_mma_gemm(
    const float* __restrict__ A, const float* __restrict__ Bt,
    const float* __restrict__ bias, float* __restrict__ C,
    int M, int N, int K)
{
    __shared__ float As[2][BM * LDT];
    __shared__ float Bs[2][BN * LDT];

    const int tid  = threadIdx.x;
    const int wid  = tid >> 5, lane = tid & 31;
    const int g    = lane >> 2, tg = lane & 3;
    const int wm   = (wid & 3) * 32;
    const int wn   = (wid >> 2) * 64;
    const int m0   = blockIdx.y * BM, n0 = blockIdx.x * BN;

    const int lr = tid >> 2;
    const int lc = (tid & 3) * 4;
    const float* Ag = A  + (size_t)(m0 + lr) * K + lc;
    const float* Bg = Bt + (size_t)(n0 + lr) * K + lc;

    float c[2][8][4];
#pragma unroll
    for (int i = 0; i < 2; i++)
#pragma unroll
        for (int j = 0; j < 8; j++)
#pragma unroll
            for (int r = 0; r < 4; r++) c[i][j][r] = 0.f;

    float4 ra0 = *(const float4*)(Ag);
    float4 ra1 = *(const float4*)(Ag + (size_t)64 * K);
    float4 rb0 = *(const float4*)(Bg);
    float4 rb1 = *(const float4*)(Bg + (size_t)64 * K);
    *(float4*)&As[0][lr * LDT + lc]        = ra0;
    *(float4*)&As[0][(lr + 64) * LDT + lc] = ra1;
    *(float4*)&Bs[0][lr * LDT + lc]        = rb0;
    *(float4*)&Bs[0][(lr + 64) * LDT + lc] = rb1;
    __syncthreads();

    const int niter = K / BK;
    for (int kt = 0; kt < niter; kt++) {
        const int cur = kt & 1;
        if (kt + 1 < niter) {
            const float* An = Ag + (kt + 1) * BK;
            const float* Bn = Bg + (kt + 1) * BK;
            ra0 = *(const float4*)(An);
            ra1 = *(const float4*)(An + (size_t)64 * K);
            rb0 = *(const float4*)(Bn);
            rb1 = *(const float4*)(Bn + (size_t)64 * K);
        }
#pragma unroll
        for (int kk = 0; kk < BK; kk += 8) {
            uint32_t a[2][4], b[8][2];
#pragma unroll
            for (int i = 0; i < 2; i++) {
                const int row = wm + i * 16 + g;
                a[i][0] = __float_as_uint(As[cur][row * LDT + kk + tg]);
                a[i][1] = __float_as_uint(As[cur][(row + 8) * LDT + kk + tg]);
                a[i][2] = __float_as_uint(As[cur][row * LDT + kk + tg + 4]);
                a[i][3] = __float_as_uint(As[cur][(row + 8) * LDT + kk + tg + 4]);
            }
#pragma unroll
            for (int j = 0; j < 8; j++) {
                const int col = wn + j * 8 + g;
                b[j][0] = __float_as_uint(Bs[cur][col * LDT + kk + tg]);
                b[j][1] = __float_as_uint(Bs[cur][col * LDT + kk + tg + 4]);
            }
#pragma unroll
            for (int i = 0; i < 2; i++)
#pragma unroll
                for (int j = 0; j < 8; j++)
                    MMA_TF32(c[i][j], a[i][0], a[i][1], a[i][2], a[i][3],
                             b[j][0], b[j][1]);
        }
        if (kt + 1 < niter) {
            const int nxt = cur ^ 1;
            *(float4*)&As[nxt][lr * LDT + lc]        = ra0;
            *(float4*)&As[nxt][(lr + 64) * LDT + lc] = ra1;
            *(float4*)&Bs[nxt][lr * LDT + lc]        = rb0;
            *(float4*)&Bs[nxt][(lr + 64) * LDT + lc] = rb1;
        }
        __syncthreads();
    }

#pragma unroll
    for (int i = 0; i < 2; i++) {
        const int rowa = m0 + wm + i * 16 + g;
#pragma unroll
        for (int j = 0; j < 8; j++) {
            const int col = n0 + wn + j * 8 + 2 * tg;
            const float bx = bias[col], by = bias[col + 1];
            float2 v0 = make_float2(c[i][j][0] + bx, c[i][j][1] + by);
            float2 v1 = make_float2(c[i][j][2] + bx, c[i][j][3] + by);
            *(float2*)(C + (size_t)rowa * N + col)       = v0;
            *(float2*)(C + (size_t)(rowa + 8) * N + col) = v1;
        }
    }
}

// ---------------------------------------------------------------------------
// prep kernels
// ---------------------------------------------------------------------------
__global__ void round_copy(const float4* __restrict__ in, float4* __restrict__ out, int n4) {
    int i = blockIdx.x * 256 + threadIdx.x;
    if (i < n4) {
        float4 v = in[i];
        v.x = round_tf32f(v.x); v.y = round_tf32f(v.y);
        v.z = round_tf32f(v.z); v.w = round_tf32f(v.w);
        out[i] = v;
    }
}

__global__ __launch_bounds__(256) void transpose_round(
    const float* __restrict__ in, float* __restrict__ out, int K, int N)
{
    __shared__ float t[32][33];
    int bx = blockIdx.x * 32, by = blockIdx.y * 32;
    int x = threadIdx.x, y = threadIdx.y;
#pragma unroll
    for (int i = 0; i < 32; i += 8)
        t[y + i][x] = in[(size_t)(by + y + i) * N + bx + x];
    __syncthreads();
#pragma unroll
    for (int i = 0; i < 32; i += 8)
        out[(size_t)(bx + y + i) * K + by + x] = round_tf32f(t[x][y + i]);
}

// ---------------------------------------------------------------------------
// MMA-based sliding-window attention.
// Block = 128 queries x one (b,h). 8 warps, each owns 16 query rows.
// S = Q K^T via 3xTF32. Softmax on fragments. P fragments -> A fragments via
// quad shuffles; O = P V single tf32 with V staged TRANSPOSED at stride VPAD
// (=132: key dim is 128 wide; 68 was the round-4 corruption bug).
// ---------------------------------------------------------------------------
#define APAD 68
#define VPAD 132
#define ATT_SMEM (4 * 128 * APAD * 4)

__global__ __launch_bounds__(256, 1) void attn_mma(
    const float* __restrict__ qkv,
    float* __restrict__ attn,
    float* __restrict__ head_out)
{
    extern __shared__ float sm[];
    float* Qhi = sm;
    float* Qlo = sm + 128 * APAD;
    float* Bhi = sm + 2 * 128 * APAD;   // also holds V^T [64][VPAD] in pass 2
    float* Blo = sm + 3 * 128 * APAD;

    const int qt = blockIdx.x, h = blockIdx.y, b = blockIdx.z;
    const int tid = threadIdx.x;
    const int w = tid >> 5, lane = tid & 31;
    const int g = lane >> 2, tg = lane & 3;
    const int q0 = qt * 128;
    const int r1 = w * 16 + g;
    const int r2 = r1 + 8;

    // zero this block's 128x2048 attn tile
    {
        float4* zb = (float4*)(attn + ((size_t)(b * NHEAD + h) * LSEQ + q0) * (size_t)LSEQ);
        float4 z = make_float4(0.f, 0.f, 0.f, 0.f);
        for (int i = tid; i < 128 * LSEQ / 4; i += 256) zb[i] = z;
    }

    // stage Q (scaled by 1/8, hi/lo split)
    for (int idx = tid; idx < 8192; idx += 256) {
        int row = idx >> 6, d = idx & 63;
        float v = qkv[(size_t)(b * LSEQ + q0 + row) * QKVN + h * HDIM + d] * 0.125f;
        float hi = round_tf32f(v);
        Qhi[row * APAD + d] = hi;
        Qlo[row * APAD + d] = round_tf32f(v - hi);
    }

    float p[2][16][4];
#pragma unroll
    for (int c = 0; c < 2; c++)
#pragma unroll
        for (int j = 0; j < 16; j++)
#pragma unroll
            for (int r = 0; r < 4; r++) p[c][j][r] = 0.f;

    // ---- S = Q K^T per 128-key chunk ----
#pragma unroll
    for (int c = 0; c < 2; c++) {
        const int kb = q0 + (c - 1) * 128;
        __syncthreads();
        for (int idx = tid; idx < 8192; idx += 256) {
            int row = idx >> 6, d = idx & 63;
            int kk = kb + row;
            float v = (kk >= 0)
                ? qkv[(size_t)(b * LSEQ + kk) * QKVN + DMODEL + h * HDIM + d] : 0.f;
            float hi = round_tf32f(v);
            Bhi[row * APAD + d] = hi;
            Blo[row * APAD + d] = round_tf32f(v - hi);
        }
        __syncthreads();

#pragma unroll 1
        for (int kkb = 0; kkb < 8; kkb++) {
            const int kc = kkb * 8 + tg;
            uint32_t ah0 = __float_as_uint(Qhi[r1 * APAD + kc]);
            uint32_t ah1 = __float_as_uint(Qhi[r2 * APAD + kc]);
            uint32_t ah2 = __float_as_uint(Qhi[r1 * APAD + kc + 4]);
            uint32_t ah3 = __float_as_uint(Qhi[r2 * APAD + kc + 4]);
            uint32_t al0 = __float_as_uint(Qlo[r1 * APAD + kc]);
            uint32_t al1 = __float_as_uint(Qlo[r2 * APAD + kc]);
            uint32_t al2 = __float_as_uint(Qlo[r1 * APAD + kc + 4]);
            uint32_t al3 = __float_as_uint(Qlo[r2 * APAD + kc + 4]);
#pragma unroll
            for (int j = 0; j < 16; j++) {
                const int col = j * 8 + g;
                uint32_t bh0 = __float_as_uint(Bhi[col * APAD + kc]);
                uint32_t bh1 = __float_as_uint(Bhi[col * APAD + kc + 4]);
                uint32_t bl0 = __float_as_uint(Blo[col * APAD + kc]);
                uint32_t bl1 = __float_as_uint(Blo[col * APAD + kc + 4]);
                MMA_TF32(p[c][j], ah0, ah1, ah2, ah3, bh0, bh1);
                MMA_TF32(p[c][j], ah0, ah1, ah2, ah3, bl0, bl1);
                MMA_TF32(p[c][j], al0, al1, al2, al3, bh0, bh1);
            }
        }
    }

    // ---- mask + exp + row sums ----
    float s1 = 0.f, s2 = 0.f;
#pragma unroll
    for (int c = 0; c < 2; c++)
#pragma unroll
        for (int j = 0; j < 16; j++)
#pragma unroll
            for (int e = 0; e < 2; e++) {
                int col = j * 8 + 2 * tg + e;
                int key = q0 + (c - 1) * 128 + col;
                bool v1 = (c == 0) ? (col > r1 && key >= 0) : (col <= r1);
                bool v2 = (c == 0) ? (col > r2 && key >= 0) : (col <= r2);
                float e1 = v1 ? __expf(p[c][j][e])     : 0.f;
                float e2 = v2 ? __expf(p[c][j][2 + e]) : 0.f;
                p[c][j][e]     = e1;
                p[c][j][2 + e] = e2;
                s1 += e1;
                s2 += e2;
            }
    s1 += __shfl_xor_sync(0xffffffffu, s1, 1);
    s1 += __shfl_xor_sync(0xffffffffu, s1, 2);
    s2 += __shfl_xor_sync(0xffffffffu, s2, 1);
    s2 += __shfl_xor_sync(0xffffffffu, s2, 2);
    const float i1 = 1.f / s1, i2 = 1.f / s2;

    // ---- normalize + write attn band ----
    float* arow1 = attn + ((size_t)(b * NHEAD + h) * LSEQ + q0 + r1) * (size_t)LSEQ;
    float* arow2 = attn + ((size_t)(b * NHEAD + h) * LSEQ + q0 + r2) * (size_t)LSEQ;
#pragma unroll
    for (int c = 0; c < 2; c++)
#pragma unroll
        for (int j = 0; j < 16; j++)
#pragma unroll
            for (int e = 0; e < 2; e++) {
                int col = j * 8 + 2 * tg + e;
                int key = q0 + (c - 1) * 128 + col;
                bool v1 = (c == 0) ? (col > r1 && key >= 0) : (col <= r1);
                bool v2 = (c == 0) ? (col > r2 && key >= 0) : (col <= r2);
                float n1 = p[c][j][e] * i1;
                float n2 = p[c][j][2 + e] * i2;
                p[c][j][e]     = n1;
                p[c][j][2 + e] = n2;
                if (v1) arow1[key] = n1;
                if (v2) arow2[key] = n2;
            }

    // ---- O = P V per chunk (V staged transposed [d][key] at stride VPAD) ----
    float o[8][4];
#pragma unroll
    for (int j = 0; j < 8; j++)
#pragma unroll
        for (int r = 0; r < 4; r++) o[j][r] = 0.f;

    const int srcA = 4 * g + (tg >> 1);
    const int srcB = srcA + 2;
    const bool odd = (tg & 1) != 0;

#pragma unroll
    for (int c = 0; c < 2; c++) {
        const int kb = q0 + (c - 1) * 128;
        __syncthreads();
        for (int idx = tid; idx < 8192; idx += 256) {
            int row = idx >> 6, d = idx & 63;   // row = key index within chunk
            int kk = kb + row;
            float v = (kk >= 0)
                ? qkv[(size_t)(b * LSEQ + kk) * QKVN + 2 * DMODEL + h * HDIM + d] : 0.f;
            Bhi[d * VPAD + row] = round_tf32f(v);
        }
        __syncthreads();

#pragma unroll
        for (int kk = 0; kk < 16; kk++) {
            float x0 = __shfl_sync(0xffffffffu, p[c][kk][0], srcA);
            float x1 = __shfl_sync(0xffffffffu, p[c][kk][1], srcA);
            float x2 = __shfl_sync(0xffffffffu, p[c][kk][2], srcA);
            float x3 = __shfl_sync(0xffffffffu, p[c][kk][3], srcA);
            float y0 = __shfl_sync(0xffffffffu, p[c][kk][0], srcB);
            float y1 = __shfl_sync(0xffffffffu, p[c][kk][1], srcB);
            float y2 = __shfl_sync(0xffffffffu, p[c][kk][2], srcB);
            float y3 = __shfl_sync(0xffffffffu, p[c][kk][3], srcB);
            uint32_t a0 = tf32u(odd ? x1 : x0);
            uint32_t a1 = tf32u(odd ? x3 : x2);
            uint32_t a2 = tf32u(odd ? y1 : y0);
            uint32_t a3 = tf32u(odd ? y3 : y2);
            const int kc = kk * 8 + tg;
#pragma unroll
            for (int j2 = 0; j2 < 8; j2++) {
                uint32_t b0 = __float_as_uint(Bhi[(j2 * 8 + g) * VPAD + kc]);
                uint32_t b1 = __float_as_uint(Bhi[(j2 * 8 + g) * VPAD + kc + 4]);
                MMA_TF32(o[j2], a0, a1, a2, a3, b0, b1);
            }
        }
    }

    // ---- epilogue: head_out [token, h*64+d], tf32-rounded for proj GEMM ----
#pragma unroll
    for (int j2 = 0; j2 < 8; j2++) {
        const int col = h * HDIM + j2 * 8 + 2 * tg;
        float2 v1 = make_float2(round_tf32f(o[j2][0]), round_tf32f(o[j2][1]));
        float2 v2 = make_float2(round_tf32f(o[j2][2]), round_tf32f(o[j2][3]));
        *(float2*)(head_out + (size_t)(b * LSEQ + q0 + r1) * DMODEL + col) = v1;
        *(float2*)(head_out + (size_t)(b * LSEQ + q0 + r2) * DMODEL + col) = v2;
    }
}

// ---------------------------------------------------------------------------
extern "C" void kernel_launch(void* const* d_in, const int* in_sizes, int n_in,
                              void* d_out, int out_size)
{
    const float* x      = (const float*)d_in[0];
    const float* W_qkv  = (const float*)d_in[1];
    const float* b_qkv  = (const float*)d_in[2];
    const float* W_proj = (const float*)d_in[3];
    const float* b_proj = (const float*)d_in[4];
    (void)in_sizes; (void)n_in; (void)out_size;

    float* out  = (float*)d_out;
    float* attn = out + (size_t)NBATCH * LSEQ * DMODEL;

    float *qkv = nullptr, *hout = nullptr, *x32 = nullptr, *wqkvT = nullptr, *wprojT = nullptr;
    cudaGetSymbolAddress((void**)&qkv,    g_qkv);
    cudaGetSymbolAddress((void**)&hout,   g_headout);
    cudaGetSymbolAddress((void**)&x32,    g_x32);
    cudaGetSymbolAddress((void**)&wqkvT,  g_wqkvT);
    cudaGetSymbolAddress((void**)&wprojT, g_wprojT);

    cudaFuncSetAttribute(attn_mma, cudaFuncAttributeMaxDynamicSharedMemorySize, ATT_SMEM);

    round_copy<<<(TOK * DMODEL / 4 + 255) / 256, 256>>>((const float4*)x, (float4*)x32, TOK * DMODEL / 4);
    transpose_round<<<dim3(QKVN / 32, DMODEL / 32), dim3(32, 8)>>>(W_qkv, wqkvT, DMODEL, QKVN);
    transpose_round<<<dim3(DMODEL / 32, DMODEL / 32), dim3(32, 8)>>>(W_proj, wprojT, DMODEL, DMODEL);

    tf32_mma_gemm<<<dim3(QKVN / 128, TOK / 128), 256>>>(
        x32, wqkvT, b_qkv, qkv, TOK, QKVN, DMODEL);

    attn_mma<<<dim3(LSEQ / 128, NHEAD, NBATCH), 256, ATT_SMEM>>>(qkv, attn, hout);

    tf32_mma_gemm<<<dim3(DMODEL / 128, TOK / 128), 256>>>(
        hout, wprojT, b_proj, out, TOK, DMODEL, DMODEL);
}

// round 6
// speedup vs baseline: 2.3843x; 1.1071x over previous
#include <cuda_runtime.h>
#include <math.h>
#include <stdint.h>

#define TOK    4096
#define DMODEL 1024
#define QKVN   3072
#define NHEAD  16
#define HDIM   64
#define LSEQ   2048
#define NBATCH 2

// ------------------------- static device scratch ---------------------------
__device__ float g_qkv[TOK * QKVN];
__device__ float g_headout[TOK * DMODEL];
__device__ float g_x32[TOK * DMODEL];
__device__ float g_wqkvT[QKVN * DMODEL];
__device__ float g_wprojT[DMODEL * DMODEL];

__device__ __forceinline__ float round_tf32f(float x) {
    uint32_t u;
    asm("cvt.rna.tf32.f32 %0, %1;" : "=r"(u) : "f"(x));
    return __uint_as_float(u);
}
__device__ __forceinline__ uint32_t tf32u(float x) {
    uint32_t u;
    asm("cvt.rna.tf32.f32 %0, %1;" : "=r"(u) : "f"(x));
    return u;
}
__device__ __forceinline__ void cp16(uint32_t s, const float* g) {
    asm volatile("cp.async.cg.shared.global [%0], [%1], 16;" :: "r"(s), "l"(g));
}

#define MMA_TF32(C, A0, A1, A2, A3, B0, B1)                                    \
    asm volatile(                                                              \
        "mma.sync.aligned.m16n8k8.row.col.f32.tf32.tf32.f32 "                  \
        "{%0,%1,%2,%3}, {%4,%5,%6,%7}, {%8,%9}, {%0,%1,%2,%3};"                \
        : "+f"((C)[0]), "+f"((C)[1]), "+f"((C)[2]), "+f"((C)[3])               \
        : "r"(A0), "r"(A1), "r"(A2), "r"(A3), "r"(B0), "r"(B1))

// ---------------------------------------------------------------------------
// tf32 mma.sync GEMM with cp.async 3-stage pipeline.
// C[M,N] = A[M,K] @ Bt[N,K]^T + bias[N]. CTA 128x128x16, 8 warps (4Mx2N),
// warp tile 32x64. Stage = As[128*20] + Bs[128*20] floats (20.0 KB).
// ---------------------------------------------------------------------------
#define BM 128
#define BN 128
#define BK 16
#define LDT 20
#define STAGES 3
#define SSTRF (2 * 128 * LDT)              // floats per stage
#define GEMM_SMEM (STAGES * SSTRF * 4)     // bytes

__global__ __launch_bounds__(256, 2) void tf32_mma_gemm(
    const float* __restrict__ A, const float* __restrict__ Bt,
    const float* __restrict__ bias, float* __restrict__ C,
    int M, int N, int K)
{
    extern __shared__ float gs[];

    const int tid  = threadIdx.x;
    const int wid  = tid >> 5, lane = tid & 31;
    const int g    = lane >> 2, tg = lane & 3;
    const int wm   = (wid & 3) * 32;
    const int wn   = (wid >> 2) * 64;
    const int m0   = blockIdx.y * BM, n0 = blockIdx.x * BN;

    const int lr = tid >> 2;
    const int lc = (tid & 3) * 4;
    const float* Ag = A  + (size_t)(m0 + lr) * K + lc;
    const float* Bg = Bt + (size_t)(n0 + lr) * K + lc;

    const uint32_t sbase = (uint32_t)__cvta_generic_to_shared(gs);
    const uint32_t sA0 = sbase + (uint32_t)((lr * LDT + lc) * 4);
    const uint32_t sA1 = sbase + (uint32_t)(((lr + 64) * LDT + lc) * 4);
    const uint32_t sB0 = sA0 + 128 * LDT * 4;
    const uint32_t sB1 = sA1 + 128 * LDT * 4;

    float c[2][8][4];
#pragma unroll
    for (int i = 0; i < 2; i++)
#pragma unroll
        for (int j = 0; j < 8; j++)
#pragma unroll
            for (int r = 0; r < 4; r++) c[i][j][r] = 0.f;

    const int niter = K / BK;

    // prologue: stages 0..STAGES-2
#pragma unroll
    for (int s = 0; s < STAGES - 1; s++) {
        const uint32_t so = (uint32_t)(s * SSTRF * 4);
        cp16(sA0 + so, Ag + s * BK);
        cp16(sA1 + so, Ag + s * BK + (size_t)64 * K);
        cp16(sB0 + so, Bg + s * BK);
        cp16(sB1 + so, Bg + s * BK + (size_t)64 * K);
        asm volatile("cp.async.commit_group;");
    }

    for (int kt = 0; kt < niter; kt++) {
        asm volatile("cp.async.wait_group %0;" :: "n"(STAGES - 2));
        __syncthreads();

        const int cur = kt % STAGES;
        const float* As = gs + cur * SSTRF;
        const float* Bs = As + 128 * LDT;

#pragma unroll
        for (int kk = 0; kk < BK; kk += 8) {
            uint32_t a[2][4], b[8][2];
#pragma unroll
            for (int i = 0; i < 2; i++) {
                const int row = wm + i * 16 + g;
                a[i][0] = __float_as_uint(As[row * LDT + kk + tg]);
                a[i][1] = __float_as_uint(As[(row + 8) * LDT + kk + tg]);
                a[i][2] = __float_as_uint(As[row * LDT + kk + tg + 4]);
                a[i][3] = __float_as_uint(As[(row + 8) * LDT + kk + tg + 4]);
            }
#pragma unroll
            for (int j = 0; j < 8; j++) {
                const int col = wn + j * 8 + g;
                b[j][0] = __float_as_uint(Bs[col * LDT + kk + tg]);
                b[j][1] = __float_as_uint(Bs[col * LDT + kk + tg + 4]);
            }
#pragma unroll
            for (int i = 0; i < 2; i++)
#pragma unroll
                for (int j = 0; j < 8; j++)
                    MMA_TF32(c[i][j], a[i][0], a[i][1], a[i][2], a[i][3],
                             b[j][0], b[j][1]);
        }

        const int nk = kt + STAGES - 1;
        if (nk < niter) {
            const int ns = nk % STAGES;
            const uint32_t so = (uint32_t)(ns * SSTRF * 4);
            cp16(sA0 + so, Ag + nk * BK);
            cp16(sA1 + so, Ag + nk * BK + (size_t)64 * K);
            cp16(sB0 + so, Bg + nk * BK);
            cp16(sB1 + so, Bg + nk * BK + (size_t)64 * K);
        }
        asm volatile("cp.async.commit_group;");
    }

#pragma unroll
    for (int i = 0; i < 2; i++) {
        const int rowa = m0 + wm + i * 16 + g;
#pragma unroll
        for (int j = 0; j < 8; j++) {
            const int col = n0 + wn + j * 8 + 2 * tg;
            const float bx = bias[col], by = bias[col + 1];
            float2 v0 = make_float2(c[i][j][0] + bx, c[i][j][1] + by);
            float2 v1 = make_float2(c[i][j][2] + bx, c[i][j][3] + by);
            *(float2*)(C + (size_t)rowa * N + col)       = v0;
            *(float2*)(C + (size_t)(rowa + 8) * N + col) = v1;
        }
    }
}

// ---------------------------------------------------------------------------
// prep kernels
// ---------------------------------------------------------------------------
__global__ void round_copy(const float4* __restrict__ in, float4* __restrict__ out, int n4) {
    int i = blockIdx.x * 256 + threadIdx.x;
    if (i < n4) {
        float4 v = in[i];
        v.x = round_tf32f(v.x); v.y = round_tf32f(v.y);
        v.z = round_tf32f(v.z); v.w = round_tf32f(v.w);
        out[i] = v;
    }
}

__global__ __launch_bounds__(256) void transpose_round(
    const float* __restrict__ in, float* __restrict__ out, int K, int N)
{
    __shared__ float t[32][33];
    int bx = blockIdx.x * 32, by = blockIdx.y * 32;
    int x = threadIdx.x, y = threadIdx.y;
#pragma unroll
    for (int i = 0; i < 32; i += 8)
        t[y + i][x] = in[(size_t)(by + y + i) * N + bx + x];
    __syncthreads();
#pragma unroll
    for (int i = 0; i < 32; i += 8)
        out[(size_t)(bx + y + i) * K + by + x] = round_tf32f(t[x][y + i]);
}

// ---------------------------------------------------------------------------
// MMA-based sliding-window attention with single-pass attn-row writes.
// After softmax, normalized P tiles are parked in smem (chunk0 -> Q region,
// chunk1 -> B region, stride PPAD) and each 2048-wide attn row is composed
// and written ONCE, fully coalesced (zeros + band inline).
// ---------------------------------------------------------------------------
#define APAD 68
#define VPAD 132
#define PPAD 132
#define ATT_SMEM (4 * 128 * APAD * 4)

__global__ __launch_bounds__(256, 1) void attn_mma(
    const float* __restrict__ qkv,
    float* __restrict__ attn,
    float* __restrict__ head_out)
{
    extern __shared__ float sm[];
    float* Qhi = sm;
    float* Qlo = sm + 128 * APAD;
    float* Bhi = sm + 2 * 128 * APAD;   // V^T [64][VPAD] in PV phase
    float* Blo = sm + 3 * 128 * APAD;
    float* P0  = sm;                    // P chunk0 [128][PPAD] (Q region dead)
    float* P1  = sm + 2 * 128 * APAD;   // P chunk1 [128][PPAD] (B region)

    const int qt = blockIdx.x, h = blockIdx.y, b = blockIdx.z;
    const int tid = threadIdx.x;
    const int w = tid >> 5, lane = tid & 31;
    const int g = lane >> 2, tg = lane & 3;
    const int q0 = qt * 128;
    const int r1 = w * 16 + g;
    const int r2 = r1 + 8;

    // stage Q (scaled by 1/8, hi/lo split)
    for (int idx = tid; idx < 8192; idx += 256) {
        int row = idx >> 6, d = idx & 63;
        float v = qkv[(size_t)(b * LSEQ + q0 + row) * QKVN + h * HDIM + d] * 0.125f;
        float hi = round_tf32f(v);
        Qhi[row * APAD + d] = hi;
        Qlo[row * APAD + d] = round_tf32f(v - hi);
    }

    float p[2][16][4];
#pragma unroll
    for (int c = 0; c < 2; c++)
#pragma unroll
        for (int j = 0; j < 16; j++)
#pragma unroll
            for (int r = 0; r < 4; r++) p[c][j][r] = 0.f;

    // ---- S = Q K^T per 128-key chunk (3xTF32) ----
#pragma unroll
    for (int c = 0; c < 2; c++) {
        const int kb = q0 + (c - 1) * 128;
        __syncthreads();
        for (int idx = tid; idx < 8192; idx += 256) {
            int row = idx >> 6, d = idx & 63;
            int kk = kb + row;
            float v = (kk >= 0)
                ? qkv[(size_t)(b * LSEQ + kk) * QKVN + DMODEL + h * HDIM + d] : 0.f;
            float hi = round_tf32f(v);
            Bhi[row * APAD + d] = hi;
            Blo[row * APAD + d] = round_tf32f(v - hi);
        }
        __syncthreads();

#pragma unroll 1
        for (int kkb = 0; kkb < 8; kkb++) {
            const int kc = kkb * 8 + tg;
            uint32_t ah0 = __float_as_uint(Qhi[r1 * APAD + kc]);
            uint32_t ah1 = __float_as_uint(Qhi[r2 * APAD + kc]);
            uint32_t ah2 = __float_as_uint(Qhi[r1 * APAD + kc + 4]);
            uint32_t ah3 = __float_as_uint(Qhi[r2 * APAD + kc + 4]);
            uint32_t al0 = __float_as_uint(Qlo[r1 * APAD + kc]);
            uint32_t al1 = __float_as_uint(Qlo[r2 * APAD + kc]);
            uint32_t al2 = __float_as_uint(Qlo[r1 * APAD + kc + 4]);
            uint32_t al3 = __float_as_uint(Qlo[r2 * APAD + kc + 4]);
#pragma unroll
            for (int j = 0; j < 16; j++) {
                const int col = j * 8 + g;
                uint32_t bh0 = __float_as_uint(Bhi[col * APAD + kc]);
                uint32_t bh1 = __float_as_uint(Bhi[col * APAD + kc + 4]);
                uint32_t bl0 = __float_as_uint(Blo[col * APAD + kc]);
                uint32_t bl1 = __float_as_uint(Blo[col * APAD + kc + 4]);
                MMA_TF32(p[c][j], ah0, ah1, ah2, ah3, bh0, bh1);
                MMA_TF32(p[c][j], ah0, ah1, ah2, ah3, bl0, bl1);
                MMA_TF32(p[c][j], al0, al1, al2, al3, bh0, bh1);
            }
        }
    }

    // ---- mask + exp + row sums ----
    float s1 = 0.f, s2 = 0.f;
#pragma unroll
    for (int c = 0; c < 2; c++)
#pragma unroll
        for (int j = 0; j < 16; j++)
#pragma unroll
            for (int e = 0; e < 2; e++) {
                int col = j * 8 + 2 * tg + e;
                int key = q0 + (c - 1) * 128 + col;
                bool v1 = (c == 0) ? (col > r1 && key >= 0) : (col <= r1);
                bool v2 = (c == 0) ? (col > r2 && key >= 0) : (col <= r2);
                float e1 = v1 ? __expf(p[c][j][e])     : 0.f;
                float e2 = v2 ? __expf(p[c][j][2 + e]) : 0.f;
                p[c][j][e]     = e1;
                p[c][j][2 + e] = e2;
                s1 += e1;
                s2 += e2;
            }
    s1 += __shfl_xor_sync(0xffffffffu, s1, 1);
    s1 += __shfl_xor_sync(0xffffffffu, s1, 2);
    s2 += __shfl_xor_sync(0xffffffffu, s2, 1);
    s2 += __shfl_xor_sync(0xffffffffu, s2, 2);
    const float i1 = 1.f / s1, i2 = 1.f / s2;

    // ---- normalize in regs + park P tiles in smem ----
    __syncthreads();   // all warps done reading Q/K tiles before overwrite
#pragma unroll
    for (int c = 0; c < 2; c++) {
        float* Pt = (c == 0) ? P0 : P1;
#pragma unroll
        for (int j = 0; j < 16; j++)
#pragma unroll
            for (int e = 0; e < 2; e++) {
                int col = j * 8 + 2 * tg + e;
                float n1 = p[c][j][e] * i1;
                float n2 = p[c][j][2 + e] * i2;
                p[c][j][e]     = n1;
                p[c][j][2 + e] = n2;
                Pt[r1 * PPAD + col] = n1;
                Pt[r2 * PPAD + col] = n2;
            }
    }
    __syncthreads();

    // ---- single coalesced pass: write full attn rows (zeros + band) ----
    {
        float* abase = attn + ((size_t)(b * NHEAD + h) * LSEQ + q0) * (size_t)LSEQ;
        const int rel0 = q0 - 128;
        for (int idx = tid; idx < 128 * (LSEQ / 4); idx += 256) {
            int row = idx >> 9;               // LSEQ/4 = 512 groups per row
            int c4  = (idx & 511) * 4;
            int rel = c4 - rel0;
            float4 v = make_float4(0.f, 0.f, 0.f, 0.f);
            if ((unsigned)rel < 128u)
                v = *(const float4*)&P0[row * PPAD + rel];
            else if ((unsigned)(rel - 128) < 128u)
                v = *(const float4*)&P1[row * PPAD + rel - 128];
            *(float4*)(abase + (size_t)row * LSEQ + c4) = v;
        }
    }

    // ---- O = P V per chunk (V staged transposed [d][key] at stride VPAD) ----
    float o[8][4];
#pragma unroll
    for (int j = 0; j < 8; j++)
#pragma unroll
        for (int r = 0; r < 4; r++) o[j][r] = 0.f;

    const int srcA = 4 * g + (tg >> 1);
    const int srcB = srcA + 2;
    const bool odd = (tg & 1) != 0;

#pragma unroll
    for (int c = 0; c < 2; c++) {
        const int kb = q0 + (c - 1) * 128;
        __syncthreads();
        for (int idx = tid; idx < 8192; idx += 256) {
            int row = idx >> 6, d = idx & 63;
            int kk = kb + row;
            float v = (kk >= 0)
                ? qkv[(size_t)(b * LSEQ + kk) * QKVN + 2 * DMODEL + h * HDIM + d] : 0.f;
            Bhi[d * VPAD + row] = round_tf32f(v);
        }
        __syncthreads();

#pragma unroll
        for (int kk = 0; kk < 16; kk++) {
            float x0 = __shfl_sync(0xffffffffu, p[c][kk][0], srcA);
            float x1 = __shfl_sync(0xffffffffu, p[c][kk][1], srcA);
            float x2 = __shfl_sync(0xffffffffu, p[c][kk][2], srcA);
            float x3 = __shfl_sync(0xffffffffu, p[c][kk][3], srcA);
            float y0 = __shfl_sync(0xffffffffu, p[c][kk][0], srcB);
            float y1 = __shfl_sync(0xffffffffu, p[c][kk][1], srcB);
            float y2 = __shfl_sync(0xffffffffu, p[c][kk][2], srcB);
            float y3 = __shfl_sync(0xffffffffu, p[c][kk][3], srcB);
            uint32_t a0 = tf32u(odd ? x1 : x0);
            uint32_t a1 = tf32u(odd ? x3 : x2);
            uint32_t a2 = tf32u(odd ? y1 : y0);
            uint32_t a3 = tf32u(odd ? y3 : y2);
            const int kc = kk * 8 + tg;
#pragma unroll
            for (int j2 = 0; j2 < 8; j2++) {
                uint32_t b0 = __float_as_uint(Bhi[(j2 * 8 + g) * VPAD + kc]);
                uint32_t b1 = __float_as_uint(Bhi[(j2 * 8 + g) * VPAD + kc + 4]);
                MMA_TF32(o[j2], a0, a1, a2, a3, b0, b1);
            }
        }
    }

    // ---- epilogue: head_out [token, h*64+d], tf32-rounded ----
#pragma unroll
    for (int j2 = 0; j2 < 8; j2++) {
        const int col = h * HDIM + j2 * 8 + 2 * tg;
        float2 v1 = make_float2(round_tf32f(o[j2][0]), round_tf32f(o[j2][1]));
        float2 v2 = make_float2(round_tf32f(o[j2][2]), round_tf32f(o[j2][3]));
        *(float2*)(head_out + (size_t)(b * LSEQ + q0 + r1) * DMODEL + col) = v1;
        *(float2*)(head_out + (size_t)(b * LSEQ + q0 + r2) * DMODEL + col) = v2;
    }
}

// ---------------------------------------------------------------------------
extern "C" void kernel_launch(void* const* d_in, const int* in_sizes, int n_in,
                              void* d_out, int out_size)
{
    const float* x      = (const float*)d_in[0];
    const float* W_qkv  = (const float*)d_in[1];
    const float* b_qkv  = (const float*)d_in[2];
    const float* W_proj = (const float*)d_in[3];
    const float* b_proj = (const float*)d_in[4];
    (void)in_sizes; (void)n_in; (void)out_size;

    float* out  = (float*)d_out;
    float* attn = out + (size_t)NBATCH * LSEQ * DMODEL;

    float *qkv = nullptr, *hout = nullptr, *x32 = nullptr, *wqkvT = nullptr, *wprojT = nullptr;
    cudaGetSymbolAddress((void**)&qkv,    g_qkv);
    cudaGetSymbolAddress((void**)&hout,   g_headout);
    cudaGetSymbolAddress((void**)&x32,    g_x32);
    cudaGetSymbolAddress((void**)&wqkvT,  g_wqkvT);
    cudaGetSymbolAddress((void**)&wprojT, g_wprojT);

    cudaFuncSetAttribute(attn_mma, cudaFuncAttributeMaxDynamicSharedMemorySize, ATT_SMEM);
    cudaFuncSetAttribute(tf32_mma_gemm, cudaFuncAttributeMaxDynamicSharedMemorySize, GEMM_SMEM);

    round_copy<<<(TOK * DMODEL / 4 + 255) / 256, 256>>>((const float4*)x, (float4*)x32, TOK * DMODEL / 4);
    transpose_round<<<dim3(QKVN / 32, DMODEL / 32), dim3(32, 8)>>>(W_qkv, wqkvT, DMODEL, QKVN);
    transpose_round<<<dim3(DMODEL / 32, DMODEL / 32), dim3(32, 8)>>>(W_proj, wprojT, DMODEL, DMODEL);

    tf32_mma_gemm<<<dim3(QKVN / 128, TOK / 128), 256, GEMM_SMEM>>>(
        x32, wqkvT, b_qkv, qkv, TOK, QKVN, DMODEL);

    attn_mma<<<dim3(LSEQ / 128, NHEAD, NBATCH), 256, ATT_SMEM>>>(qkv, attn, hout);

    tf32_mma_gemm<<<dim3(DMODEL / 128, TOK / 128), 256, GEMM_SMEM>>>(
        hout, wprojT, b_proj, out, TOK, DMODEL, DMODEL);
}

// round 7
// speedup vs baseline: 2.7193x; 1.1405x over previous
#include <cuda_runtime.h>
#include <math.h>
#include <stdint.h>

#define TOK    4096
#define DMODEL 1024
#define QKVN   3072
#define NHEAD  16
#define HDIM   64
#define LSEQ   2048
#define NBATCH 2

// ------------------------- static device scratch ---------------------------
__device__ float g_qkv[TOK * QKVN];
__device__ float g_headout[TOK * DMODEL];
__device__ float g_x32[TOK * DMODEL];
__device__ float g_wqkvT[QKVN * DMODEL];
__device__ float g_wprojT[DMODEL * DMODEL];

__device__ __forceinline__ float round_tf32f(float x) {
    uint32_t u;
    asm("cvt.rna.tf32.f32 %0, %1;" : "=r"(u) : "f"(x));
    return __uint_as_float(u);
}
__device__ __forceinline__ uint32_t tf32u(float x) {
    uint32_t u;
    asm("cvt.rna.tf32.f32 %0, %1;" : "=r"(u) : "f"(x));
    return u;
}
__device__ __forceinline__ void cp16(uint32_t s, const float* g) {
    asm volatile("cp.async.cg.shared.global [%0], [%1], 16;" :: "r"(s), "l"(g));
}

#define MMA_TF32(C, A0, A1, A2, A3, B0, B1)                                    \
    asm volatile(                                                              \
        "mma.sync.aligned.m16n8k8.row.col.f32.tf32.tf32.f32 "                  \
        "{%0,%1,%2,%3}, {%4,%5,%6,%7}, {%8,%9}, {%0,%1,%2,%3};"                \
        : "+f"((C)[0]), "+f"((C)[1]), "+f"((C)[2]), "+f"((C)[3])               \
        : "r"(A0), "r"(A1), "r"(A2), "r"(A3), "r"(B0), "r"(B1))

// ---------------------------------------------------------------------------
// tf32 mma.sync GEMM with cp.async 3-stage pipeline (unchanged from round 6)
// ---------------------------------------------------------------------------
#define BM 128
#define BN 128
#define BK 16
#define LDT 20
#define STAGES 3
#define SSTRF (2 * 128 * LDT)
#define GEMM_SMEM (STAGES * SSTRF * 4)

__global__ __launch_bounds__(256, 2) void tf32_mma_gemm(
    const float* __restrict__ A, const float* __restrict__ Bt,
    const float* __restrict__ bias, float* __restrict__ C,
    int M, int N, int K)
{
    extern __shared__ float gs[];

    const int tid  = threadIdx.x;
    const int wid  = tid >> 5, lane = tid & 31;
    const int g    = lane >> 2, tg = lane & 3;
    const int wm   = (wid & 3) * 32;
    const int wn   = (wid >> 2) * 64;
    const int m0   = blockIdx.y * BM, n0 = blockIdx.x * BN;

    const int lr = tid >> 2;
    const int lc = (tid & 3) * 4;
    const float* Ag = A  + (size_t)(m0 + lr) * K + lc;
    const float* Bg = Bt + (size_t)(n0 + lr) * K + lc;

    const uint32_t sbase = (uint32_t)__cvta_generic_to_shared(gs);
    const uint32_t sA0 = sbase + (uint32_t)((lr * LDT + lc) * 4);
    const uint32_t sA1 = sbase + (uint32_t)(((lr + 64) * LDT + lc) * 4);
    const uint32_t sB0 = sA0 + 128 * LDT * 4;
    const uint32_t sB1 = sA1 + 128 * LDT * 4;

    float c[2][8][4];
#pragma unroll
    for (int i = 0; i < 2; i++)
#pragma unroll
        for (int j = 0; j < 8; j++)
#pragma unroll
            for (int r = 0; r < 4; r++) c[i][j][r] = 0.f;

    const int niter = K / BK;

#pragma unroll
    for (int s = 0; s < STAGES - 1; s++) {
        const uint32_t so = (uint32_t)(s * SSTRF * 4);
        cp16(sA0 + so, Ag + s * BK);
        cp16(sA1 + so, Ag + s * BK + (size_t)64 * K);
        cp16(sB0 + so, Bg + s * BK);
        cp16(sB1 + so, Bg + s * BK + (size_t)64 * K);
        asm volatile("cp.async.commit_group;");
    }

    for (int kt = 0; kt < niter; kt++) {
        asm volatile("cp.async.wait_group %0;" :: "n"(STAGES - 2));
        __syncthreads();

        const int cur = kt % STAGES;
        const float* As = gs + cur * SSTRF;
        const float* Bs = As + 128 * LDT;

#pragma unroll
        for (int kk = 0; kk < BK; kk += 8) {
            uint32_t a[2][4], b[8][2];
#pragma unroll
            for (int i = 0; i < 2; i++) {
                const int row = wm + i * 16 + g;
                a[i][0] = __float_as_uint(As[row * LDT + kk + tg]);
                a[i][1] = __float_as_uint(As[(row + 8) * LDT + kk + tg]);
                a[i][2] = __float_as_uint(As[row * LDT + kk + tg + 4]);
                a[i][3] = __float_as_uint(As[(row + 8) * LDT + kk + tg + 4]);
            }
#pragma unroll
            for (int j = 0; j < 8; j++) {
                const int col = wn + j * 8 + g;
                b[j][0] = __float_as_uint(Bs[col * LDT + kk + tg]);
                b[j][1] = __float_as_uint(Bs[col * LDT + kk + tg + 4]);
            }
#pragma unroll
            for (int i = 0; i < 2; i++)
#pragma unroll
                for (int j = 0; j < 8; j++)
                    MMA_TF32(c[i][j], a[i][0], a[i][1], a[i][2], a[i][3],
                             b[j][0], b[j][1]);
        }

        const int nk = kt + STAGES - 1;
        if (nk < niter) {
            const int ns = nk % STAGES;
            const uint32_t so = (uint32_t)(ns * SSTRF * 4);
            cp16(sA0 + so, Ag + nk * BK);
            cp16(sA1 + so, Ag + nk * BK + (size_t)64 * K);
            cp16(sB0 + so, Bg + nk * BK);
            cp16(sB1 + so, Bg + nk * BK + (size_t)64 * K);
        }
        asm volatile("cp.async.commit_group;");
    }

#pragma unroll
    for (int i = 0; i < 2; i++) {
        const int rowa = m0 + wm + i * 16 + g;
#pragma unroll
        for (int j = 0; j < 8; j++) {
            const int col = n0 + wn + j * 8 + 2 * tg;
            const float bx = bias[col], by = bias[col + 1];
            float2 v0 = make_float2(c[i][j][0] + bx, c[i][j][1] + by);
            float2 v1 = make_float2(c[i][j][2] + bx, c[i][j][3] + by);
            *(float2*)(C + (size_t)rowa * N + col)       = v0;
            *(float2*)(C + (size_t)(rowa + 8) * N + col) = v1;
        }
    }
}

// ---------------------------------------------------------------------------
// prep kernels
// ---------------------------------------------------------------------------
__global__ void round_copy(const float4* __restrict__ in, float4* __restrict__ out, int n4) {
    int i = blockIdx.x * 256 + threadIdx.x;
    if (i < n4) {
        float4 v = in[i];
        v.x = round_tf32f(v.x); v.y = round_tf32f(v.y);
        v.z = round_tf32f(v.z); v.w = round_tf32f(v.w);
        out[i] = v;
    }
}

__global__ __launch_bounds__(256) void transpose_round(
    const float* __restrict__ in, float* __restrict__ out, int K, int N)
{
    __shared__ float t[32][33];
    int bx = blockIdx.x * 32, by = blockIdx.y * 32;
    int x = threadIdx.x, y = threadIdx.y;
#pragma unroll
    for (int i = 0; i < 32; i += 8)
        t[y + i][x] = in[(size_t)(by + y + i) * N + bx + x];
    __syncthreads();
#pragma unroll
    for (int i = 0; i < 32; i += 8)
        out[(size_t)(bx + y + i) * K + by + x] = round_tf32f(t[x][y + i]);
}

// ---------------------------------------------------------------------------
// Sliding-window attention v2: 512 threads = 16 warps (8 query-stripes x
// 2 key-halves). Single-tf32 scores. Normalized P parked in smem and used as
// BOTH the gmem write source (two per-row-contiguous coalesced slabs) AND the
// PV A-operand source (no accumulator->operand shuffles).
// smem (floats): SQ[128*68] | SK[128*68] ; SP[128*132] overlays SQ+SK after S;
// SV[64*132] ; SE[128*68] (row sums, then O exchange).
// ---------------------------------------------------------------------------
#define QK 68
#define PP 132
#define SM_SQ 0
#define SM_SK (128 * QK)              // 8704
#define SM_SP 0                        // park overlays SQ+SK (needs 16896 <= 17408)
#define SM_SV (2 * 128 * QK)           // 17408
#define SM_SE (SM_SV + 64 * PP)        // 25856
#define ATT_FLOATS (SM_SE + 128 * QK)  // 34560
#define ATT_SMEM (ATT_FLOATS * 4)      // 138240 B

__global__ __launch_bounds__(512, 1) void attn_mma(
    const float* __restrict__ qkv,
    float* __restrict__ attn,
    float* __restrict__ head_out)
{
    extern __shared__ float sm[];
    float* SQ = sm + SM_SQ;
    float* SK = sm + SM_SK;
    float* SP = sm + SM_SP;
    float* SV = sm + SM_SV;
    float* SE = sm + SM_SE;

    const int qt = blockIdx.x, h = blockIdx.y, b = blockIdx.z;
    const int tid = threadIdx.x;
    const int w = tid >> 5, lane = tid & 31;
    const int wq = w & 7, wk = w >> 3;
    const int g = lane >> 2, tg = lane & 3;
    const int q0 = qt * 128;
    const int r1 = wq * 16 + g;
    const int r2 = r1 + 8;

    // ---- stage Q (float4, scaled 1/8, tf32-rounded) ----
    for (int idx = tid; idx < 2048; idx += 512) {
        int row = idx >> 4, d4 = (idx & 15) << 2;
        float4 v = *(const float4*)(qkv + (size_t)(b * LSEQ + q0 + row) * QKVN + h * HDIM + d4);
        v.x = round_tf32f(v.x * 0.125f);
        v.y = round_tf32f(v.y * 0.125f);
        v.z = round_tf32f(v.z * 0.125f);
        v.w = round_tf32f(v.w * 0.125f);
        *(float4*)&SQ[row * QK + d4] = v;
    }

    float p[2][8][4];
#pragma unroll
    for (int c = 0; c < 2; c++)
#pragma unroll
        for (int j = 0; j < 8; j++)
#pragma unroll
            for (int r = 0; r < 4; r++) p[c][j][r] = 0.f;

    // ---- S = Q K^T per chunk, single tf32 ----
#pragma unroll
    for (int c = 0; c < 2; c++) {
        const int kb = q0 + (c - 1) * 128;
        __syncthreads();
        for (int idx = tid; idx < 2048; idx += 512) {
            int row = idx >> 4, d4 = (idx & 15) << 2;
            int kk = kb + row;
            float4 v = make_float4(0.f, 0.f, 0.f, 0.f);
            if (kk >= 0)
                v = *(const float4*)(qkv + (size_t)(b * LSEQ + kk) * QKVN + DMODEL + h * HDIM + d4);
            v.x = round_tf32f(v.x); v.y = round_tf32f(v.y);
            v.z = round_tf32f(v.z); v.w = round_tf32f(v.w);
            *(float4*)&SK[row * QK + d4] = v;
        }
        __syncthreads();

#pragma unroll
        for (int kkb = 0; kkb < 8; kkb++) {
            const int kc = kkb * 8 + tg;
            uint32_t a0 = __float_as_uint(SQ[r1 * QK + kc]);
            uint32_t a1 = __float_as_uint(SQ[r2 * QK + kc]);
            uint32_t a2 = __float_as_uint(SQ[r1 * QK + kc + 4]);
            uint32_t a3 = __float_as_uint(SQ[r2 * QK + kc + 4]);
#pragma unroll
            for (int j = 0; j < 8; j++) {
                const int col = wk * 64 + j * 8 + g;
                uint32_t b0 = __float_as_uint(SK[col * QK + kc]);
                uint32_t b1 = __float_as_uint(SK[col * QK + kc + 4]);
                MMA_TF32(p[c][j], a0, a1, a2, a3, b0, b1);
            }
        }
    }

    // ---- mask + exp + partial row sums (quad-reduced) ----
    float s1 = 0.f, s2 = 0.f;
#pragma unroll
    for (int c = 0; c < 2; c++)
#pragma unroll
        for (int j = 0; j < 8; j++)
#pragma unroll
            for (int e = 0; e < 2; e++) {
                int colc = wk * 64 + j * 8 + 2 * tg + e;
                int key = q0 + (c - 1) * 128 + colc;
                bool v1 = (c == 0) ? (colc > r1 && key >= 0) : (colc <= r1);
                bool v2 = (c == 0) ? (colc > r2 && key >= 0) : (colc <= r2);
                float e1 = v1 ? __expf(p[c][j][e])     : 0.f;
                float e2 = v2 ? __expf(p[c][j][2 + e]) : 0.f;
                p[c][j][e]     = e1;
                p[c][j][2 + e] = e2;
                s1 += e1;
                s2 += e2;
            }
    s1 += __shfl_xor_sync(0xffffffffu, s1, 1);
    s1 += __shfl_xor_sync(0xffffffffu, s1, 2);
    s2 += __shfl_xor_sync(0xffffffffu, s2, 1);
    s2 += __shfl_xor_sync(0xffffffffu, s2, 2);
    if (tg == 0) {
        SE[wk * 128 + r1] = s1;
        SE[wk * 128 + r2] = s2;
    }
    __syncthreads();
    const float i1 = 1.f / (SE[r1] + SE[128 + r1]);
    const float i2 = 1.f / (SE[r2] + SE[128 + r2]);

    float o[8][4];
#pragma unroll
    for (int j = 0; j < 8; j++)
#pragma unroll
        for (int r = 0; r < 4; r++) o[j][r] = 0.f;

    float* abase = attn + ((size_t)(b * NHEAD + h) * LSEQ + q0) * (size_t)LSEQ;

    // ---- per chunk: park normalized P -> slab write + PV ----
#pragma unroll
    for (int c = 0; c < 2; c++) {
        const int kb = q0 + (c - 1) * 128;
        __syncthreads();   // c=0: S/sum reads done; c=1: slab-A + PV0 reads of SP done

        // park normalized P (float2 stores; masked entries are exact zeros)
#pragma unroll
        for (int j = 0; j < 8; j++) {
            const int colc = wk * 64 + j * 8 + 2 * tg;
            *(float2*)&SP[r1 * PP + colc] = make_float2(p[c][j][0] * i1, p[c][j][1] * i1);
            *(float2*)&SP[r2 * PP + colc] = make_float2(p[c][j][2] * i2, p[c][j][3] * i2);
        }

        // stage V^T [d][key] (tf32-rounded)
        for (int idx = tid; idx < 2048; idx += 512) {
            int key = idx >> 4, d4 = (idx & 15) << 2;
            int kk = kb + key;
            float4 v = make_float4(0.f, 0.f, 0.f, 0.f);
            if (kk >= 0)
                v = *(const float4*)(qkv + (size_t)(b * LSEQ + kk) * QKVN + 2 * DMODEL + h * HDIM + d4);
            SV[(d4 + 0) * PP + key] = round_tf32f(v.x);
            SV[(d4 + 1) * PP + key] = round_tf32f(v.y);
            SV[(d4 + 2) * PP + key] = round_tf32f(v.z);
            SV[(d4 + 3) * PP + key] = round_tf32f(v.w);
        }
        __syncthreads();

        // coalesced slab write: c=0 -> cols [0,q0), c=1 -> cols [q0,2048)
        if (c == 0) {
            const int n4 = q0 >> 2;
            const int rel0 = q0 - 128;
            for (int idx = tid; idx < 128 * n4; idx += 512) {
                int row = idx / n4;
                int col = (idx - row * n4) << 2;
                int rel = col - rel0;
                float4 v = make_float4(0.f, 0.f, 0.f, 0.f);
                if (rel >= 0) v = *(const float4*)&SP[row * PP + rel];
                *(float4*)(abase + (size_t)row * LSEQ + col) = v;
            }
        } else {
            const int n4 = (LSEQ - q0) >> 2;
            for (int idx = tid; idx < 128 * n4; idx += 512) {
                int row = idx / n4;
                int rel = (idx - row * n4) << 2;
                float4 v = make_float4(0.f, 0.f, 0.f, 0.f);
                if (rel < 128) v = *(const float4*)&SP[row * PP + rel];
                *(float4*)(abase + (size_t)row * LSEQ + q0 + rel) = v;
            }
        }

        // PV partial: this warp handles keys [wk*64, wk*64+64) of the chunk
#pragma unroll
        for (int kk = 0; kk < 8; kk++) {
            const int kc = wk * 64 + kk * 8 + tg;
            uint32_t a0 = tf32u(SP[r1 * PP + kc]);
            uint32_t a1 = tf32u(SP[r2 * PP + kc]);
            uint32_t a2 = tf32u(SP[r1 * PP + kc + 4]);
            uint32_t a3 = tf32u(SP[r2 * PP + kc + 4]);
#pragma unroll
            for (int j2 = 0; j2 < 8; j2++) {
                const int d = j2 * 8 + g;
                uint32_t b0 = __float_as_uint(SV[d * PP + kc]);
                uint32_t b1 = __float_as_uint(SV[d * PP + kc + 4]);
                MMA_TF32(o[j2], a0, a1, a2, a3, b0, b1);
            }
        }
    }

    // ---- O exchange between wk halves; wk=1 writes head_out ----
    __syncthreads();
    if (wk == 0) {
#pragma unroll
        for (int j2 = 0; j2 < 8; j2++) {
            const int col = j2 * 8 + 2 * tg;
            *(float2*)&SE[r1 * QK + col] = make_float2(o[j2][0], o[j2][1]);
            *(float2*)&SE[r2 * QK + col] = make_float2(o[j2][2], o[j2][3]);
        }
    }
    __syncthreads();
    if (wk == 1) {
#pragma unroll
        for (int j2 = 0; j2 < 8; j2++) {
            const int col = j2 * 8 + 2 * tg;
            float2 e1 = *(const float2*)&SE[r1 * QK + col];
            float2 e2 = *(const float2*)&SE[r2 * QK + col];
            float2 v1 = make_float2(round_tf32f(o[j2][0] + e1.x), round_tf32f(o[j2][1] + e1.y));
            float2 v2 = make_float2(round_tf32f(o[j2][2] + e2.x), round_tf32f(o[j2][3] + e2.y));
            *(float2*)(head_out + (size_t)(b * LSEQ + q0 + r1) * DMODEL + h * HDIM + col) = v1;
            *(float2*)(head_out + (size_t)(b * LSEQ + q0 + r2) * DMODEL + h * HDIM + col) = v2;
        }
    }
}

// ---------------------------------------------------------------------------
extern "C" void kernel_launch(void* const* d_in, const int* in_sizes, int n_in,
                              void* d_out, int out_size)
{
    const float* x      = (const float*)d_in[0];
    const float* W_qkv  = (const float*)d_in[1];
    const float* b_qkv  = (const float*)d_in[2];
    const float* W_proj = (const float*)d_in[3];
    const float* b_proj = (const float*)d_in[4];
    (void)in_sizes; (void)n_in; (void)out_size;

    float* out  = (float*)d_out;
    float* attn = out + (size_t)NBATCH * LSEQ * DMODEL;

    float *qkv = nullptr, *hout = nullptr, *x32 = nullptr, *wqkvT = nullptr, *wprojT = nullptr;
    cudaGetSymbolAddress((void**)&qkv,    g_qkv);
    cudaGetSymbolAddress((void**)&hout,   g_headout);
    cudaGetSymbolAddress((void**)&x32,    g_x32);
    cudaGetSymbolAddress((void**)&wqkvT,  g_wqkvT);
    cudaGetSymbolAddress((void**)&wprojT, g_wprojT);

    cudaFuncSetAttribute(attn_mma, cudaFuncAttributeMaxDynamicSharedMemorySize, ATT_SMEM);
    cudaFuncSetAttribute(tf32_mma_gemm, cudaFuncAttributeMaxDynamicSharedMemorySize, GEMM_SMEM);

    round_copy<<<(TOK * DMODEL / 4 + 255) / 256, 256>>>((const float4*)x, (float4*)x32, TOK * DMODEL / 4);
    transpose_round<<<dim3(QKVN / 32, DMODEL / 32), dim3(32, 8)>>>(W_qkv, wqkvT, DMODEL, QKVN);
    transpose_round<<<dim3(DMODEL / 32, DMODEL / 32), dim3(32, 8)>>>(W_proj, wprojT, DMODEL, DMODEL);

    tf32_mma_gemm<<<dim3(QKVN / 128, TOK / 128), 256, GEMM_SMEM>>>(
        x32, wqkvT, b_qkv, qkv, TOK, QKVN, DMODEL);

    attn_mma<<<dim3(LSEQ / 128, NHEAD, NBATCH), 512, ATT_SMEM>>>(qkv, attn, hout);

    tf32_mma_gemm<<<dim3(DMODEL / 128, TOK / 128), 256, GEMM_SMEM>>>(
        hout, wprojT, b_proj, out, TOK, DMODEL, DMODEL);
}

// round 8
// speedup vs baseline: 3.0888x; 1.1359x over previous
#include <cuda_runtime.h>
#include <math.h>
#include <stdint.h>

#define TOK    4096
#define DMODEL 1024
#define QKVN   3072
#define NHEAD  16
#define HDIM   64
#define LSEQ   2048
#define NBATCH 2

// ------------------------- static device scratch ---------------------------
__device__ float g_qkv[TOK * QKVN];
__device__ float g_headout[TOK * DMODEL];
__device__ float g_x32[TOK * DMODEL];
__device__ float g_wqkvT[QKVN * DMODEL];
__device__ float g_wprojT[DMODEL * DMODEL];

__device__ __forceinline__ float round_tf32f(float x) {
    uint32_t u;
    asm("cvt.rna.tf32.f32 %0, %1;" : "=r"(u) : "f"(x));
    return __uint_as_float(u);
}
__device__ __forceinline__ uint32_t tf32u(float x) {
    uint32_t u;
    asm("cvt.rna.tf32.f32 %0, %1;" : "=r"(u) : "f"(x));
    return u;
}
__device__ __forceinline__ void cp16(uint32_t s, const float* g) {
    asm volatile("cp.async.cg.shared.global [%0], [%1], 16;" :: "r"(s), "l"(g));
}
__device__ __forceinline__ void ldsm4(uint32_t& r0, uint32_t& r1, uint32_t& r2,
                                      uint32_t& r3, uint32_t addr) {
    asm volatile("ldmatrix.sync.aligned.m8n8.x4.shared.b16 {%0,%1,%2,%3}, [%4];"
                 : "=r"(r0), "=r"(r1), "=r"(r2), "=r"(r3) : "r"(addr));
}

#define MMA_TF32(C, A0, A1, A2, A3, B0, B1)                                    \
    asm volatile(                                                              \
        "mma.sync.aligned.m16n8k8.row.col.f32.tf32.tf32.f32 "                  \
        "{%0,%1,%2,%3}, {%4,%5,%6,%7}, {%8,%9}, {%0,%1,%2,%3};"                \
        : "+f"((C)[0]), "+f"((C)[1]), "+f"((C)[2]), "+f"((C)[3])               \
        : "r"(A0), "r"(A1), "r"(A2), "r"(A3), "r"(B0), "r"(B1))

// ---------------------------------------------------------------------------
// tf32 mma.sync GEMM, cp.async 3-stage pipeline, ldmatrix fragment loads.
// C[M,N] = A[M,K] @ Bt[N,K]^T + bias[N]. CTA 128x128x16, 8 warps (4Mx2N),
// warp tile 32x64. SMEM K-major rows, stride LDT=20 floats (ldmatrix
// conflict-free: 20i mod 32 distinct for i=0..7).
// ---------------------------------------------------------------------------
#define BM 128
#define BN 128
#define BK 16
#define LDT 20
#define STAGES 3
#define SSTRF (2 * 128 * LDT)
#define GEMM_SMEM (STAGES * SSTRF * 4)

__global__ __launch_bounds__(256, 2) void tf32_mma_gemm(
    const float* __restrict__ A, const float* __restrict__ Bt,
    const float* __restrict__ bias, float* __restrict__ C,
    int M, int N, int K)
{
    extern __shared__ float gs[];

    const int tid  = threadIdx.x;
    const int wid  = tid >> 5, lane = tid & 31;
    const int g    = lane >> 2, tg = lane & 3;
    const int wm   = (wid & 3) * 32;
    const int wn   = (wid >> 2) * 64;
    const int m0   = blockIdx.y * BM, n0 = blockIdx.x * BN;

    const int lr = tid >> 2;
    const int lc = (tid & 3) * 4;
    const float* Ag = A  + (size_t)(m0 + lr) * K + lc;
    const float* Bg = Bt + (size_t)(n0 + lr) * K + lc;

    const uint32_t sbase = (uint32_t)__cvta_generic_to_shared(gs);
    const uint32_t sA0 = sbase + (uint32_t)((lr * LDT + lc) * 4);
    const uint32_t sA1 = sbase + (uint32_t)(((lr + 64) * LDT + lc) * 4);
    const uint32_t sB0 = sA0 + 128 * LDT * 4;
    const uint32_t sB1 = sA1 + 128 * LDT * 4;

    // ldmatrix lane offsets (bytes, relative to stage base)
    const int q   = lane >> 3;     // quad: selects matrix within .x4
    const int lr8 = lane & 7;      // row within matrix
    // A: m0..3 = {rows+0 k0, rows+8 k0, rows+0 k4, rows+8 k4}
    const uint32_t offA0 = (uint32_t)(((wm + (q & 1) * 8 + lr8) * LDT + (q >> 1) * 4) * 4);
    const uint32_t offA1 = offA0 + 16 * LDT * 4;
    // B: m0..3 = {col+0 k0, col+0 k4, col+8 k0, col+8 k4}
    const uint32_t offB  = (uint32_t)(((wn + (q >> 1) * 8 + lr8) * LDT + (q & 1) * 4) * 4)
                           + 128 * LDT * 4;

    float c[2][8][4];
#pragma unroll
    for (int i = 0; i < 2; i++)
#pragma unroll
        for (int j = 0; j < 8; j++)
#pragma unroll
            for (int r = 0; r < 4; r++) c[i][j][r] = 0.f;

    const int niter = K / BK;

#pragma unroll
    for (int s = 0; s < STAGES - 1; s++) {
        const uint32_t so = (uint32_t)(s * SSTRF * 4);
        cp16(sA0 + so, Ag + s * BK);
        cp16(sA1 + so, Ag + s * BK + (size_t)64 * K);
        cp16(sB0 + so, Bg + s * BK);
        cp16(sB1 + so, Bg + s * BK + (size_t)64 * K);
        asm volatile("cp.async.commit_group;");
    }

    for (int kt = 0; kt < niter; kt++) {
        asm volatile("cp.async.wait_group %0;" :: "n"(STAGES - 2));
        __syncthreads();

        const uint32_t sb = sbase + (uint32_t)((kt % STAGES) * SSTRF * 4);

#pragma unroll
        for (int kk = 0; kk < BK; kk += 8) {
            const uint32_t koff = kk * 4;
            uint32_t a[2][4], b[8][2];
            ldsm4(a[0][0], a[0][1], a[0][2], a[0][3], sb + offA0 + koff);
            ldsm4(a[1][0], a[1][1], a[1][2], a[1][3], sb + offA1 + koff);
#pragma unroll
            for (int jj = 0; jj < 4; jj++)
                ldsm4(b[2 * jj][0], b[2 * jj][1], b[2 * jj + 1][0], b[2 * jj + 1][1],
                      sb + offB + (uint32_t)(jj * 16 * LDT * 4) + koff);
#pragma unroll
            for (int i = 0; i < 2; i++)
#pragma unroll
                for (int j = 0; j < 8; j++)
                    MMA_TF32(c[i][j], a[i][0], a[i][1], a[i][2], a[i][3],
                             b[j][0], b[j][1]);
        }

        const int nk = kt + STAGES - 1;
        if (nk < niter) {
            const int ns = nk % STAGES;
            const uint32_t so = (uint32_t)(ns * SSTRF * 4);
            cp16(sA0 + so, Ag + nk * BK);
            cp16(sA1 + so, Ag + nk * BK + (size_t)64 * K);
            cp16(sB0 + so, Bg + nk * BK);
            cp16(sB1 + so, Bg + nk * BK + (size_t)64 * K);
        }
        asm volatile("cp.async.commit_group;");
    }

#pragma unroll
    for (int i = 0; i < 2; i++) {
        const int rowa = m0 + wm + i * 16 + g;
#pragma unroll
        for (int j = 0; j < 8; j++) {
            const int col = n0 + wn + j * 8 + 2 * tg;
            const float bx = bias[col], by = bias[col + 1];
            float2 v0 = make_float2(c[i][j][0] + bx, c[i][j][1] + by);
            float2 v1 = make_float2(c[i][j][2] + bx, c[i][j][3] + by);
            *(float2*)(C + (size_t)rowa * N + col)       = v0;
            *(float2*)(C + (size_t)(rowa + 8) * N + col) = v1;
        }
    }
}

// ---------------------------------------------------------------------------
// prep kernels
// ---------------------------------------------------------------------------
__global__ void round_copy(const float4* __restrict__ in, float4* __restrict__ out, int n4) {
    int i = blockIdx.x * 256 + threadIdx.x;
    if (i < n4) {
        float4 v = in[i];
        v.x = round_tf32f(v.x); v.y = round_tf32f(v.y);
        v.z = round_tf32f(v.z); v.w = round_tf32f(v.w);
        out[i] = v;
    }
}

__global__ __launch_bounds__(256) void transpose_round(
    const float* __restrict__ in, float* __restrict__ out, int K, int N)
{
    __shared__ float t[32][33];
    int bx = blockIdx.x * 32, by = blockIdx.y * 32;
    int x = threadIdx.x, y = threadIdx.y;
#pragma unroll
    for (int i = 0; i < 32; i += 8)
        t[y + i][x] = in[(size_t)(by + y + i) * N + bx + x];
    __syncthreads();
#pragma unroll
    for (int i = 0; i < 32; i += 8)
        out[(size_t)(bx + y + i) * K + by + x] = round_tf32f(t[x][y + i]);
}

// ---------------------------------------------------------------------------
// Sliding-window attention v2 (unchanged from round 7).
// ---------------------------------------------------------------------------
#define QK 68
#define PP 132
#define SM_SQ 0
#define SM_SK (128 * QK)
#define SM_SP 0
#define SM_SV (2 * 128 * QK)
#define SM_SE (SM_SV + 64 * PP)
#define ATT_FLOATS (SM_SE + 128 * QK)
#define ATT_SMEM (ATT_FLOATS * 4)

__global__ __launch_bounds__(512, 1) void attn_mma(
    const float* __restrict__ qkv,
    float* __restrict__ attn,
    float* __restrict__ head_out)
{
    extern __shared__ float sm[];
    float* SQ = sm + SM_SQ;
    float* SK = sm + SM_SK;
    float* SP = sm + SM_SP;
    float* SV = sm + SM_SV;
    float* SE = sm + SM_SE;

    const int qt = blockIdx.x, h = blockIdx.y, b = blockIdx.z;
    const int tid = threadIdx.x;
    const int w = tid >> 5, lane = tid & 31;
    const int wq = w & 7, wk = w >> 3;
    const int g = lane >> 2, tg = lane & 3;
    const int q0 = qt * 128;
    const int r1 = wq * 16 + g;
    const int r2 = r1 + 8;

    for (int idx = tid; idx < 2048; idx += 512) {
        int row = idx >> 4, d4 = (idx & 15) << 2;
        float4 v = *(const float4*)(qkv + (size_t)(b * LSEQ + q0 + row) * QKVN + h * HDIM + d4);
        v.x = round_tf32f(v.x * 0.125f);
        v.y = round_tf32f(v.y * 0.125f);
        v.z = round_tf32f(v.z * 0.125f);
        v.w = round_tf32f(v.w * 0.125f);
        *(float4*)&SQ[row * QK + d4] = v;
    }

    float p[2][8][4];
#pragma unroll
    for (int c = 0; c < 2; c++)
#pragma unroll
        for (int j = 0; j < 8; j++)
#pragma unroll
            for (int r = 0; r < 4; r++) p[c][j][r] = 0.f;

#pragma unroll
    for (int c = 0; c < 2; c++) {
        const int kb = q0 + (c - 1) * 128;
        __syncthreads();
        for (int idx = tid; idx < 2048; idx += 512) {
            int row = idx >> 4, d4 = (idx & 15) << 2;
            int kk = kb + row;
            float4 v = make_float4(0.f, 0.f, 0.f, 0.f);
            if (kk >= 0)
                v = *(const float4*)(qkv + (size_t)(b * LSEQ + kk) * QKVN + DMODEL + h * HDIM + d4);
            v.x = round_tf32f(v.x); v.y = round_tf32f(v.y);
            v.z = round_tf32f(v.z); v.w = round_tf32f(v.w);
            *(float4*)&SK[row * QK + d4] = v;
        }
        __syncthreads();

#pragma unroll
        for (int kkb = 0; kkb < 8; kkb++) {
            const int kc = kkb * 8 + tg;
            uint32_t a0 = __float_as_uint(SQ[r1 * QK + kc]);
            uint32_t a1 = __float_as_uint(SQ[r2 * QK + kc]);
            uint32_t a2 = __float_as_uint(SQ[r1 * QK + kc + 4]);
            uint32_t a3 = __float_as_uint(SQ[r2 * QK + kc + 4]);
#pragma unroll
            for (int j = 0; j < 8; j++) {
                const int col = wk * 64 + j * 8 + g;
                uint32_t b0 = __float_as_uint(SK[col * QK + kc]);
                uint32_t b1 = __float_as_uint(SK[col * QK + kc + 4]);
                MMA_TF32(p[c][j], a0, a1, a2, a3, b0, b1);
            }
        }
    }

    float s1 = 0.f, s2 = 0.f;
#pragma unroll
    for (int c = 0; c < 2; c++)
#pragma unroll
        for (int j = 0; j < 8; j++)
#pragma unroll
            for (int e = 0; e < 2; e++) {
                int colc = wk * 64 + j * 8 + 2 * tg + e;
                int key = q0 + (c - 1) * 128 + colc;
                bool v1 = (c == 0) ? (colc > r1 && key >= 0) : (colc <= r1);
                bool v2 = (c == 0) ? (colc > r2 && key >= 0) : (colc <= r2);
                float e1 = v1 ? __expf(p[c][j][e])     : 0.f;
                float e2 = v2 ? __expf(p[c][j][2 + e]) : 0.f;
                p[c][j][e]     = e1;
                p[c][j][2 + e] = e2;
                s1 += e1;
                s2 += e2;
            }
    s1 += __shfl_xor_sync(0xffffffffu, s1, 1);
    s1 += __shfl_xor_sync(0xffffffffu, s1, 2);
    s2 += __shfl_xor_sync(0xffffffffu, s2, 1);
    s2 += __shfl_xor_sync(0xffffffffu, s2, 2);
    if (tg == 0) {
        SE[wk * 128 + r1] = s1;
        SE[wk * 128 + r2] = s2;
    }
    __syncthreads();
    const float i1 = 1.f / (SE[r1] + SE[128 + r1]);
    const float i2 = 1.f / (SE[r2] + SE[128 + r2]);

    float o[8][4];
#pragma unroll
    for (int j = 0; j < 8; j++)
#pragma unroll
        for (int r = 0; r < 4; r++) o[j][r] = 0.f;

    float* abase = attn + ((size_t)(b * NHEAD + h) * LSEQ + q0) * (size_t)LSEQ;

#pragma unroll
    for (int c = 0; c < 2; c++) {
        const int kb = q0 + (c - 1) * 128;
        __syncthreads();

#pragma unroll
        for (int j = 0; j < 8; j++) {
            const int colc = wk * 64 + j * 8 + 2 * tg;
            *(float2*)&SP[r1 * PP + colc] = make_float2(p[c][j][0] * i1, p[c][j][1] * i1);
            *(float2*)&SP[r2 * PP + colc] = make_float2(p[c][j][2] * i2, p[c][j][3] * i2);
        }

        for (int idx = tid; idx < 2048; idx += 512) {
            int key = idx >> 4, d4 = (idx & 15) << 2;
            int kk = kb + key;
            float4 v = make_float4(0.f, 0.f, 0.f, 0.f);
            if (kk >= 0)
                v = *(const float4*)(qkv + (size_t)(b * LSEQ + kk) * QKVN + 2 * DMODEL + h * HDIM + d4);
            SV[(d4 + 0) * PP + key] = round_tf32f(v.x);
            SV[(d4 + 1) * PP + key] = round_tf32f(v.y);
            SV[(d4 + 2) * PP + key] = round_tf32f(v.z);
            SV[(d4 + 3) * PP + key] = round_tf32f(v.w);
        }
        __syncthreads();

        if (c == 0) {
            const int n4 = q0 >> 2;
            const int rel0 = q0 - 128;
            for (int idx = tid; idx < 128 * n4; idx += 512) {
                int row = idx / n4;
                int col = (idx - row * n4) << 2;
                int rel = col - rel0;
                float4 v = make_float4(0.f, 0.f, 0.f, 0.f);
                if (rel >= 0) v = *(const float4*)&SP[row * PP + rel];
                *(float4*)(abase + (size_t)row * LSEQ + col) = v;
            }
        } else {
            const int n4 = (LSEQ - q0) >> 2;
            for (int idx = tid; idx < 128 * n4; idx += 512) {
                int row = idx / n4;
                int rel = (idx - row * n4) << 2;
                float4 v = make_float4(0.f, 0.f, 0.f, 0.f);
                if (rel < 128) v = *(const float4*)&SP[row * PP + rel];
                *(float4*)(abase + (size_t)row * LSEQ + q0 + rel) = v;
            }
        }

#pragma unroll
        for (int kk = 0; kk < 8; kk++) {
            const int kc = wk * 64 + kk * 8 + tg;
            uint32_t a0 = tf32u(SP[r1 * PP + kc]);
            uint32_t a1 = tf32u(SP[r2 * PP + kc]);
            uint32_t a2 = tf32u(SP[r1 * PP + kc + 4]);
            uint32_t a3 = tf32u(SP[r2 * PP + kc + 4]);
#pragma unroll
            for (int j2 = 0; j2 < 8; j2++) {
                const int d = j2 * 8 + g;
                uint32_t b0 = __float_as_uint(SV[d * PP + kc]);
                uint32_t b1 = __float_as_uint(SV[d * PP + kc + 4]);
                MMA_TF32(o[j2], a0, a1, a2, a3, b0, b1);
            }
        }
    }

    __syncthreads();
    if (wk == 0) {
#pragma unroll
        for (int j2 = 0; j2 < 8; j2++) {
            const int col = j2 * 8 + 2 * tg;
            *(float2*)&SE[r1 * QK + col] = make_float2(o[j2][0], o[j2][1]);
            *(float2*)&SE[r2 * QK + col] = make_float2(o[j2][2], o[j2][3]);
        }
    }
    __syncthreads();
    if (wk == 1) {
#pragma unroll
        for (int j2 = 0; j2 < 8; j2++) {
            const int col = j2 * 8 + 2 * tg;
            float2 e1 = *(const float2*)&SE[r1 * QK + col];
            float2 e2 = *(const float2*)&SE[r2 * QK + col];
            float2 v1 = make_float2(round_tf32f(o[j2][0] + e1.x), round_tf32f(o[j2][1] + e1.y));
            float2 v2 = make_float2(round_tf32f(o[j2][2] + e2.x), round_tf32f(o[j2][3] + e2.y));
            *(float2*)(head_out + (size_t)(b * LSEQ + q0 + r1) * DMODEL + h * HDIM + col) = v1;
            *(float2*)(head_out + (size_t)(b * LSEQ + q0 + r2) * DMODEL + h * HDIM + col) = v2;
        }
    }
}

// ---------------------------------------------------------------------------
extern "C" void kernel_launch(void* const* d_in, const int* in_sizes, int n_in,
                              void* d_out, int out_size)
{
    const float* x      = (const float*)d_in[0];
    const float* W_qkv  = (const float*)d_in[1];
    const float* b_qkv  = (const float*)d_in[2];
    const float* W_proj = (const float*)d_in[3];
    const float* b_proj = (const float*)d_in[4];
    (void)in_sizes; (void)n_in; (void)out_size;

    float* out  = (float*)d_out;
    float* attn = out + (size_t)NBATCH * LSEQ * DMODEL;

    float *qkv = nullptr, *hout = nullptr, *x32 = nullptr, *wqkvT = nullptr, *wprojT = nullptr;
    cudaGetSymbolAddress((void**)&qkv,    g_qkv);
    cudaGetSymbolAddress((void**)&hout,   g_headout);
    cudaGetSymbolAddress((void**)&x32,    g_x32);
    cudaGetSymbolAddress((void**)&wqkvT,  g_wqkvT);
    cudaGetSymbolAddress((void**)&wprojT, g_wprojT);

    cudaFuncSetAttribute(attn_mma, cudaFuncAttributeMaxDynamicSharedMemorySize, ATT_SMEM);
    cudaFuncSetAttribute(tf32_mma_gemm, cudaFuncAttributeMaxDynamicSharedMemorySize, GEMM_SMEM);

    round_copy<<<(TOK * DMODEL / 4 + 255) / 256, 256>>>((const float4*)x, (float4*)x32, TOK * DMODEL / 4);
    transpose_round<<<dim3(QKVN / 32, DMODEL / 32), dim3(32, 8)>>>(W_qkv, wqkvT, DMODEL, QKVN);
    transpose_round<<<dim3(DMODEL / 32, DMODEL / 32), dim3(32, 8)>>>(W_proj, wprojT, DMODEL, DMODEL);

    tf32_mma_gemm<<<dim3(QKVN / 128, TOK / 128), 256, GEMM_SMEM>>>(
        x32, wqkvT, b_qkv, qkv, TOK, QKVN, DMODEL);

    attn_mma<<<dim3(LSEQ / 128, NHEAD, NBATCH), 512, ATT_SMEM>>>(qkv, attn, hout);

    tf32_mma_gemm<<<dim3(DMODEL / 128, TOK / 128), 256, GEMM_SMEM>>>(
        hout, wprojT, b_proj, out, TOK, DMODEL, DMODEL);
}

// round 9
// speedup vs baseline: 3.0920x; 1.0010x over previous
#include <cuda_runtime.h>
#include <math.h>
#include <stdint.h>

#define TOK    4096
#define DMODEL 1024
#define QKVN   3072
#define NHEAD  16
#define HDIM   64
#define LSEQ   2048
#define NBATCH 2

// ------------------------- static device scratch ---------------------------
__device__ float g_qkv[TOK * QKVN];
__device__ float g_headout[TOK * DMODEL];
__device__ float g_x32[TOK * DMODEL];
__device__ float g_wqkvT[QKVN * DMODEL];
__device__ float g_wprojT[DMODEL * DMODEL];

__device__ __forceinline__ float round_tf32f(float x) {
    uint32_t u;
    asm("cvt.rna.tf32.f32 %0, %1;" : "=r"(u) : "f"(x));
    return __uint_as_float(u);
}
__device__ __forceinline__ uint32_t tf32u(float x) {
    uint32_t u;
    asm("cvt.rna.tf32.f32 %0, %1;" : "=r"(u) : "f"(x));
    return u;
}
__device__ __forceinline__ void cp16(uint32_t s, const float* g) {
    asm volatile("cp.async.cg.shared.global [%0], [%1], 16;" :: "r"(s), "l"(g));
}
__device__ __forceinline__ void ldsm4(uint32_t& r0, uint32_t& r1, uint32_t& r2,
                                      uint32_t& r3, uint32_t addr) {
    asm volatile("ldmatrix.sync.aligned.m8n8.x4.shared.b16 {%0,%1,%2,%3}, [%4];"
                 : "=r"(r0), "=r"(r1), "=r"(r2), "=r"(r3) : "r"(addr));
}

#define MMA_TF32(C, A0, A1, A2, A3, B0, B1)                                    \
    asm volatile(                                                              \
        "mma.sync.aligned.m16n8k8.row.col.f32.tf32.tf32.f32 "                  \
        "{%0,%1,%2,%3}, {%4,%5,%6,%7}, {%8,%9}, {%0,%1,%2,%3};"                \
        : "+f"((C)[0]), "+f"((C)[1]), "+f"((C)[2]), "+f"((C)[3])               \
        : "r"(A0), "r"(A1), "r"(A2), "r"(A3), "r"(B0), "r"(B1))

// ---------------------------------------------------------------------------
// tf32 mma.sync GEMM: BK=32, 2-stage cp.async pipeline, ldmatrix frag loads.
// C[M,N] = A[M,K] @ Bt[N,K]^T + bias[N]. CTA 128x128x32, 8 warps (4Mx2N).
// SMEM K-major rows, stride LDT=36 (36i mod 32 distinct -> ldmatrix clean).
// One __syncthreads + one wait_group per 64 MMAs (was per 32).
// ---------------------------------------------------------------------------
#define BM 128
#define BN 128
#define BK 32
#define LDT 36
#define STAGES 2
#define SSTRF (2 * 128 * LDT)
#define GEMM_SMEM (STAGES * SSTRF * 4)

__global__ __launch_bounds__(256, 2) void tf32_mma_gemm(
    const float* __restrict__ A, const float* __restrict__ Bt,
    const float* __restrict__ bias, float* __restrict__ C,
    int M, int N, int K)
{
    extern __shared__ float gs[];

    const int tid  = threadIdx.x;
    const int wid  = tid >> 5, lane = tid & 31;
    const int g    = lane >> 2, tg = lane & 3;
    const int wm   = (wid & 3) * 32;
    const int wn   = (wid >> 2) * 64;
    const int m0   = blockIdx.y * BM, n0 = blockIdx.x * BN;

    // cp.async mapping: 1024 float4 slots per tile; thread t does slots t+256i
    const uint32_t sbase = (uint32_t)__cvta_generic_to_shared(gs);

    // ldmatrix lane offsets (bytes, relative to stage base)
    const int q   = lane >> 3;
    const int lr8 = lane & 7;
    const uint32_t offA0 = (uint32_t)(((wm + (q & 1) * 8 + lr8) * LDT + (q >> 1) * 4) * 4);
    const uint32_t offA1 = offA0 + 16 * LDT * 4;
    const uint32_t offB  = (uint32_t)(((wn + (q >> 1) * 8 + lr8) * LDT + (q & 1) * 4) * 4)
                           + 128 * LDT * 4;

    float c[2][8][4];
#pragma unroll
    for (int i = 0; i < 2; i++)
#pragma unroll
        for (int j = 0; j < 8; j++)
#pragma unroll
            for (int r = 0; r < 4; r++) c[i][j][r] = 0.f;

    const int niter = K / BK;

    // slot geometry: row = s >> 3 (0..127), c4 = (s & 7) * 4
    const int s0row = tid >> 3, s0c = (tid & 7) * 4;

    // prologue: stage 0
#pragma unroll
    for (int i = 0; i < 4; i++) {
        const int row = s0row + i * 32;
        const uint32_t so = (uint32_t)((row * LDT + s0c) * 4);
        cp16(sbase + so, A + (size_t)(m0 + row) * K + s0c);
        cp16(sbase + so + 128 * LDT * 4, Bt + (size_t)(n0 + row) * K + s0c);
    }
    asm volatile("cp.async.commit_group;");

    for (int kt = 0; kt < niter; kt++) {
        asm volatile("cp.async.wait_group 0;");
        __syncthreads();

        // issue next stage loads (hidden behind this iteration's 64 MMAs)
        if (kt + 1 < niter) {
            const uint32_t st = (uint32_t)(((kt + 1) & 1) * SSTRF * 4);
            const int kb = (kt + 1) * BK;
#pragma unroll
            for (int i = 0; i < 4; i++) {
                const int row = s0row + i * 32;
                const uint32_t so = st + (uint32_t)((row * LDT + s0c) * 4);
                cp16(sbase + so, A + (size_t)(m0 + row) * K + kb + s0c);
                cp16(sbase + so + 128 * LDT * 4, Bt + (size_t)(n0 + row) * K + kb + s0c);
            }
        }
        asm volatile("cp.async.commit_group;");

        const uint32_t sb = sbase + (uint32_t)((kt & 1) * SSTRF * 4);
#pragma unroll
        for (int kk = 0; kk < BK; kk += 8) {
            const uint32_t koff = kk * 4;
            uint32_t a[2][4], b[8][2];
            ldsm4(a[0][0], a[0][1], a[0][2], a[0][3], sb + offA0 + koff);
            ldsm4(a[1][0], a[1][1], a[1][2], a[1][3], sb + offA1 + koff);
#pragma unroll
            for (int jj = 0; jj < 4; jj++)
                ldsm4(b[2 * jj][0], b[2 * jj][1], b[2 * jj + 1][0], b[2 * jj + 1][1],
                      sb + offB + (uint32_t)(jj * 16 * LDT * 4) + koff);
#pragma unroll
            for (int i = 0; i < 2; i++)
#pragma unroll
                for (int j = 0; j < 8; j++)
                    MMA_TF32(c[i][j], a[i][0], a[i][1], a[i][2], a[i][3],
                             b[j][0], b[j][1]);
        }
    }

#pragma unroll
    for (int i = 0; i < 2; i++) {
        const int rowa = m0 + wm + i * 16 + g;
#pragma unroll
        for (int j = 0; j < 8; j++) {
            const int col = n0 + wn + j * 8 + 2 * tg;
            const float bx = bias[col], by = bias[col + 1];
            float2 v0 = make_float2(c[i][j][0] + bx, c[i][j][1] + by);
            float2 v1 = make_float2(c[i][j][2] + bx, c[i][j][3] + by);
            *(float2*)(C + (size_t)rowa * N + col)       = v0;
            *(float2*)(C + (size_t)(rowa + 8) * N + col) = v1;
        }
    }
}

// ---------------------------------------------------------------------------
// prep kernels
// ---------------------------------------------------------------------------
__global__ void round_copy(const float4* __restrict__ in, float4* __restrict__ out, int n4) {
    int i = blockIdx.x * 256 + threadIdx.x;
    if (i < n4) {
        float4 v = in[i];
        v.x = round_tf32f(v.x); v.y = round_tf32f(v.y);
        v.z = round_tf32f(v.z); v.w = round_tf32f(v.w);
        out[i] = v;
    }
}

__global__ __launch_bounds__(256) void transpose_round(
    const float* __restrict__ in, float* __restrict__ out, int K, int N)
{
    __shared__ float t[32][33];
    int bx = blockIdx.x * 32, by = blockIdx.y * 32;
    int x = threadIdx.x, y = threadIdx.y;
#pragma unroll
    for (int i = 0; i < 32; i += 8)
        t[y + i][x] = in[(size_t)(by + y + i) * N + bx + x];
    __syncthreads();
#pragma unroll
    for (int i = 0; i < 32; i += 8)
        out[(size_t)(bx + y + i) * K + by + x] = round_tf32f(t[x][y + i]);
}

// ---------------------------------------------------------------------------
// Sliding-window attention v2 (unchanged from round 7/8).
// ---------------------------------------------------------------------------
#define QK 68
#define PP 132
#define SM_SQ 0
#define SM_SK (128 * QK)
#define SM_SP 0
#define SM_SV (2 * 128 * QK)
#define SM_SE (SM_SV + 64 * PP)
#define ATT_FLOATS (SM_SE + 128 * QK)
#define ATT_SMEM (ATT_FLOATS * 4)

__global__ __launch_bounds__(512, 1) void attn_mma(
    const float* __restrict__ qkv,
    float* __restrict__ attn,
    float* __restrict__ head_out)
{
    extern __shared__ float sm[];
    float* SQ = sm + SM_SQ;
    float* SK = sm + SM_SK;
    float* SP = sm + SM_SP;
    float* SV = sm + SM_SV;
    float* SE = sm + SM_SE;

    const int qt = blockIdx.x, h = blockIdx.y, b = blockIdx.z;
    const int tid = threadIdx.x;
    const int w = tid >> 5, lane = tid & 31;
    const int wq = w & 7, wk = w >> 3;
    const int g = lane >> 2, tg = lane & 3;
    const int q0 = qt * 128;
    const int r1 = wq * 16 + g;
    const int r2 = r1 + 8;

    for (int idx = tid; idx < 2048; idx += 512) {
        int row = idx >> 4, d4 = (idx & 15) << 2;
        float4 v = *(const float4*)(qkv + (size_t)(b * LSEQ + q0 + row) * QKVN + h * HDIM + d4);
        v.x = round_tf32f(v.x * 0.125f);
        v.y = round_tf32f(v.y * 0.125f);
        v.z = round_tf32f(v.z * 0.125f);
        v.w = round_tf32f(v.w * 0.125f);
        *(float4*)&SQ[row * QK + d4] = v;
    }

    float p[2][8][4];
#pragma unroll
    for (int c = 0; c < 2; c++)
#pragma unroll
        for (int j = 0; j < 8; j++)
#pragma unroll
            for (int r = 0; r < 4; r++) p[c][j][r] = 0.f;

#pragma unroll
    for (int c = 0; c < 2; c++) {
        const int kb = q0 + (c - 1) * 128;
        __syncthreads();
        for (int idx = tid; idx < 2048; idx += 512) {
            int row = idx >> 4, d4 = (idx & 15) << 2;
            int kk = kb + row;
            float4 v = make_float4(0.f, 0.f, 0.f, 0.f);
            if (kk >= 0)
                v = *(const float4*)(qkv + (size_t)(b * LSEQ + kk) * QKVN + DMODEL + h * HDIM + d4);
            v.x = round_tf32f(v.x); v.y = round_tf32f(v.y);
            v.z = round_tf32f(v.z); v.w = round_tf32f(v.w);
            *(float4*)&SK[row * QK + d4] = v;
        }
        __syncthreads();

#pragma unroll
        for (int kkb = 0; kkb < 8; kkb++) {
            const int kc = kkb * 8 + tg;
            uint32_t a0 = __float_as_uint(SQ[r1 * QK + kc]);
            uint32_t a1 = __float_as_uint(SQ[r2 * QK + kc]);
            uint32_t a2 = __float_as_uint(SQ[r1 * QK + kc + 4]);
            uint32_t a3 = __float_as_uint(SQ[r2 * QK + kc + 4]);
#pragma unroll
            for (int j = 0; j < 8; j++) {
                const int col = wk * 64 + j * 8 + g;
                uint32_t b0 = __float_as_uint(SK[col * QK + kc]);
                uint32_t b1 = __float_as_uint(SK[col * QK + kc + 4]);
                MMA_TF32(p[c][j], a0, a1, a2, a3, b0, b1);
            }
        }
    }

    float s1 = 0.f, s2 = 0.f;
#pragma unroll
    for (int c = 0; c < 2; c++)
#pragma unroll
        for (int j = 0; j < 8; j++)
#pragma unroll
            for (int e = 0; e < 2; e++) {
                int colc = wk * 64 + j * 8 + 2 * tg + e;
                int key = q0 + (c - 1) * 128 + colc;
                bool v1 = (c == 0) ? (colc > r1 && key >= 0) : (colc <= r1);
                bool v2 = (c == 0) ? (colc > r2 && key >= 0) : (colc <= r2);
                float e1 = v1 ? __expf(p[c][j][e])     : 0.f;
                float e2 = v2 ? __expf(p[c][j][2 + e]) : 0.f;
                p[c][j][e]     = e1;
                p[c][j][2 + e] = e2;
                s1 += e1;
                s2 += e2;
            }
    s1 += __shfl_xor_sync(0xffffffffu, s1, 1);
    s1 += __shfl_xor_sync(0xffffffffu, s1, 2);
    s2 += __shfl_xor_sync(0xffffffffu, s2, 1);
    s2 += __shfl_xor_sync(0xffffffffu, s2, 2);
    if (tg == 0) {
        SE[wk * 128 + r1] = s1;
        SE[wk * 128 + r2] = s2;
    }
    __syncthreads();
    const float i1 = 1.f / (SE[r1] + SE[128 + r1]);
    const float i2 = 1.f / (SE[r2] + SE[128 + r2]);

    float o[8][4];
#pragma unroll
    for (int j = 0; j < 8; j++)
#pragma unroll
        for (int r = 0; r < 4; r++) o[j][r] = 0.f;

    float* abase = attn + ((size_t)(b * NHEAD + h) * LSEQ + q0) * (size_t)LSEQ;

#pragma unroll
    for (int c = 0; c < 2; c++) {
        const int kb = q0 + (c - 1) * 128;
        __syncthreads();

#pragma unroll
        for (int j = 0; j < 8; j++) {
            const int colc = wk * 64 + j * 8 + 2 * tg;
            *(float2*)&SP[r1 * PP + colc] = make_float2(p[c][j][0] * i1, p[c][j][1] * i1);
            *(float2*)&SP[r2 * PP + colc] = make_float2(p[c][j][2] * i2, p[c][j][3] * i2);
        }

        for (int idx = tid; idx < 2048; idx += 512) {
            int key = idx >> 4, d4 = (idx & 15) << 2;
            int kk = kb + key;
            float4 v = make_float4(0.f, 0.f, 0.f, 0.f);
            if (kk >= 0)
                v = *(const float4*)(qkv + (size_t)(b * LSEQ + kk) * QKVN + 2 * DMODEL + h * HDIM + d4);
            SV[(d4 + 0) * PP + key] = round_tf32f(v.x);
            SV[(d4 + 1) * PP + key] = round_tf32f(v.y);
            SV[(d4 + 2) * PP + key] = round_tf32f(v.z);
            SV[(d4 + 3) * PP + key] = round_tf32f(v.w);
        }
        __syncthreads();

        if (c == 0) {
            const int n4 = q0 >> 2;
            const int rel0 = q0 - 128;
            for (int idx = tid; idx < 128 * n4; idx += 512) {
                int row = idx / n4;
                int col = (idx - row * n4) << 2;
                int rel = col - rel0;
                float4 v = make_float4(0.f, 0.f, 0.f, 0.f);
                if (rel >= 0) v = *(const float4*)&SP[row * PP + rel];
                *(float4*)(abase + (size_t)row * LSEQ + col) = v;
            }
        } else {
            const int n4 = (LSEQ - q0) >> 2;
            for (int idx = tid; idx < 128 * n4; idx += 512) {
                int row = idx / n4;
                int rel = (idx - row * n4) << 2;
                float4 v = make_float4(0.f, 0.f, 0.f, 0.f);
                if (rel < 128) v = *(const float4*)&SP[row * PP + rel];
                *(float4*)(abase + (size_t)row * LSEQ + q0 + rel) = v;
            }
        }

#pragma unroll
        for (int kk = 0; kk < 8; kk++) {
            const int kc = wk * 64 + kk * 8 + tg;
            uint32_t a0 = tf32u(SP[r1 * PP + kc]);
            uint32_t a1 = tf32u(SP[r2 * PP + kc]);
            uint32_t a2 = tf32u(SP[r1 * PP + kc + 4]);
            uint32_t a3 = tf32u(SP[r2 * PP + kc + 4]);
#pragma unroll
            for (int j2 = 0; j2 < 8; j2++) {
                const int d = j2 * 8 + g;
                uint32_t b0 = __float_as_uint(SV[d * PP + kc]);
                uint32_t b1 = __float_as_uint(SV[d * PP + kc + 4]);
                MMA_TF32(o[j2], a0, a1, a2, a3, b0, b1);
            }
        }
    }

    __syncthreads();
    if (wk == 0) {
#pragma unroll
        for (int j2 = 0; j2 < 8; j2++) {
            const int col = j2 * 8 + 2 * tg;
            *(float2*)&SE[r1 * QK + col] = make_float2(o[j2][0], o[j2][1]);
            *(float2*)&SE[r2 * QK + col] = make_float2(o[j2][2], o[j2][3]);
        }
    }
    __syncthreads();
    if (wk == 1) {
#pragma unroll
        for (int j2 = 0; j2 < 8; j2++) {
            const int col = j2 * 8 + 2 * tg;
            float2 e1 = *(const float2*)&SE[r1 * QK + col];
            float2 e2 = *(const float2*)&SE[r2 * QK + col];
            float2 v1 = make_float2(round_tf32f(o[j2][0] + e1.x), round_tf32f(o[j2][1] + e1.y));
            float2 v2 = make_float2(round_tf32f(o[j2][2] + e2.x), round_tf32f(o[j2][3] + e2.y));
            *(float2*)(head_out + (size_t)(b * LSEQ + q0 + r1) * DMODEL + h * HDIM + col) = v1;
            *(float2*)(head_out + (size_t)(b * LSEQ + q0 + r2) * DMODEL + h * HDIM + col) = v2;
        }
    }
}

// ---------------------------------------------------------------------------
extern "C" void kernel_launch(void* const* d_in, const int* in_sizes, int n_in,
                              void* d_out, int out_size)
{
    const float* x      = (const float*)d_in[0];
    const float* W_qkv  = (const float*)d_in[1];
    const float* b_qkv  = (const float*)d_in[2];
    const float* W_proj = (const float*)d_in[3];
    const float* b_proj = (const float*)d_in[4];
    (void)in_sizes; (void)n_in; (void)out_size;

    float* out  = (float*)d_out;
    float* attn = out + (size_t)NBATCH * LSEQ * DMODEL;

    float *qkv = nullptr, *hout = nullptr, *x32 = nullptr, *wqkvT = nullptr, *wprojT = nullptr;
    cudaGetSymbolAddress((void**)&qkv,    g_qkv);
    cudaGetSymbolAddress((void**)&hout,   g_headout);
    cudaGetSymbolAddress((void**)&x32,    g_x32);
    cudaGetSymbolAddress((void**)&wqkvT,  g_wqkvT);
    cudaGetSymbolAddress((void**)&wprojT, g_wprojT);

    cudaFuncSetAttribute(attn_mma, cudaFuncAttributeMaxDynamicSharedMemorySize, ATT_SMEM);
    cudaFuncSetAttribute(tf32_mma_gemm, cudaFuncAttributeMaxDynamicSharedMemorySize, GEMM_SMEM);

    round_copy<<<(TOK * DMODEL / 4 + 255) / 256, 256>>>((const float4*)x, (float4*)x32, TOK * DMODEL / 4);
    transpose_round<<<dim3(QKVN / 32, DMODEL / 32), dim3(32, 8)>>>(W_qkv, wqkvT, DMODEL, QKVN);
    transpose_round<<<dim3(DMODEL / 32, DMODEL / 32), dim3(32, 8)>>>(W_proj, wprojT, DMODEL, DMODEL);

    tf32_mma_gemm<<<dim3(QKVN / 128, TOK / 128), 256, GEMM_SMEM>>>(
        x32, wqkvT, b_qkv, qkv, TOK, QKVN, DMODEL);

    attn_mma<<<dim3(LSEQ / 128, NHEAD, NBATCH), 512, ATT_SMEM>>>(qkv, attn, hout);

    tf32_mma_gemm<<<dim3(DMODEL / 128, TOK / 128), 256, GEMM_SMEM>>>(
        hout, wprojT, b_proj, out, TOK, DMODEL, DMODEL);
}